// round 13
// baseline (speedup 1.0000x reference)
#include <cuda_runtime.h>
#include <cuda_fp16.h>
#include <math.h>
#include <stdint.h>

#define ATTN_SCALE 0.17677669529663687f  // 32^-0.5

__device__ __forceinline__ uint32_t smem_u32(const void* p) {
    uint32_t a;
    asm("{ .reg .u64 t; cvta.to.shared.u64 t, %1; cvt.u32.u64 %0, t; }" : "=r"(a) : "l"(p));
    return a;
}
__device__ __forceinline__ void cp16(uint32_t s, const void* g) {
    asm volatile("cp.async.cg.shared.global [%0], [%1], 16;" :: "r"(s), "l"(g));
}
__device__ __forceinline__ void cp_commit() { asm volatile("cp.async.commit_group;"); }
__device__ __forceinline__ void cp_wait1() { asm volatile("cp.async.wait_group 1;"); }
__device__ __forceinline__ void ldsm4(uint32_t r[4], uint32_t addr) {
    asm volatile("ldmatrix.sync.aligned.m8n8.x4.shared.b16 {%0,%1,%2,%3}, [%4];"
                 : "=r"(r[0]), "=r"(r[1]), "=r"(r[2]), "=r"(r[3]) : "r"(addr));
}
__device__ __forceinline__ void mma16816(float c[4], const uint32_t a[4], uint32_t b0,
                                         uint32_t b1) {
    asm volatile(
        "mma.sync.aligned.m16n8k16.row.col.f32.f16.f16.f32 "
        "{%0,%1,%2,%3}, {%4,%5,%6,%7}, {%8,%9}, {%0,%1,%2,%3};"
        : "+f"(c[0]), "+f"(c[1]), "+f"(c[2]), "+f"(c[3])
        : "r"(a[0]), "r"(a[1]), "r"(a[2]), "r"(a[3]), "r"(b0), "r"(b1));
}

// =================== device scratch ===================
__device__ __half g_Xn[4096 * 256];
__device__ __half g_Wkv[1024 * 256];
__device__ float g_bcat[1024];
__device__ float g_KV[4096 * 1024];
__device__ float g_x[4096 * 256];
__device__ __half g_t16[4096 * 256];
__device__ float g_q[4096 * 256];
__device__ __half g_a16[4096 * 256];
__device__ float g_z1[4096 * 256];
__device__ float g_z2[4096 * 256];
__device__ __half g_z216[4096 * 256];
__device__ __half g_h16[4096 * 512];
__device__ float g_z3[4096 * 256];
__device__ __half g_Wq2[2 * 256 * 256];
__device__ __half g_Wp2[2 * 256 * 256];
__device__ __half g_Wm1c[2 * 512 * 256];
__device__ __half g_Wm2c[2 * 256 * 512];
__device__ int g_bcount[128];
__device__ int g_blist[127 * 128];

// =================== bucket build ===================
__global__ void bucket_zero(int* bcount) { bcount[threadIdx.x] = 0; }
__global__ void bucket_kernel(const float* __restrict__ u, int* __restrict__ bcount,
                              int* __restrict__ blist) {
    int m = blockIdx.x * 256 + threadIdx.x;
    float uf = floorf(u[m]);
    int w = (int)fminf(fmaxf(uf, 0.f), 126.f);
    int pos = atomicAdd(&bcount[w], 1);
    if (pos < 128) blist[w * 128 + pos] = m;
}

// =================== fused prep kernel (R11 version) ===================
struct WtJob { const float* src; __half* dst; int K; int N; };
struct WtJobs { WtJob j[8]; };
__global__ __launch_bounds__(256) void prep_kernel(
    const float* __restrict__ grd_x,
    const float* __restrict__ Wk, const float* __restrict__ Wv,
    const float* __restrict__ lnkw, const float* __restrict__ lnvw,
    const float* __restrict__ lnkb, const float* __restrict__ lnvb,
    __half* __restrict__ Xn, __half* __restrict__ Wkv, float* __restrict__ bcat,
    WtJobs jobs) {
    __shared__ float tile[256][33];
    __shared__ float ps[8][32], pq[8][32];
    __shared__ float cmu[32], crs[32];
    int bid = blockIdx.x;
    int tid = threadIdx.x;
    int tx = tid & 31, ty = tid >> 5;

    if (bid < 128) {
        int j0 = bid * 32;
        float s = 0.f, q = 0.f;
#pragma unroll
        for (int t = 0; t < 32; t++) {
            int c = t * 8 + ty;
            float v = grd_x[(size_t)c * 4096 + j0 + tx];
            tile[c][tx] = v;
            s += v; q += v * v;
        }
        ps[ty][tx] = s; pq[ty][tx] = q;
        __syncthreads();
        if (ty == 0) {
            float ss = 0.f, qq = 0.f;
#pragma unroll
            for (int r = 0; r < 8; r++) { ss += ps[r][tx]; qq += pq[r][tx]; }
            float mu = ss * (1.f / 256.f);
            cmu[tx] = mu;
            crs[tx] = rsqrtf(qq * (1.f / 256.f) - mu * mu + 1e-5f);
        }
        __syncthreads();
#pragma unroll
        for (int r = 0; r < 4; r++) {
            int jj = ty * 4 + r;
            float mu = cmu[jj], rs = crs[jj];
            size_t rb = (size_t)(j0 + jj) * 256 + tx * 8;
            __half h[8];
#pragma unroll
            for (int e = 0; e < 8; e++)
                h[e] = __float2half_rn((tile[tx * 8 + e][jj] - mu) * rs);
            *(uint4*)(Xn + rb) = *(uint4*)h;
        }
    } else if (bid < 384) {
        int local = bid - 128;
        int ct = local & 7, ot = (local >> 3) & 7, seg = local >> 6;
        int i = seg >> 1, isv = seg & 1;
        const float* W = (isv ? Wv : Wk) + i * 65536;
        const float* lw = (isv ? lnvw : lnkw) + i * 256;
        int c0 = ct * 32, o0 = ot * 32;
        float (*t)[33] = (float (*)[33])tile;
#pragma unroll
        for (int s = 0; s < 4; s++) {
            int c = c0 + ty + s * 8;
            t[ty + s * 8][tx] = W[(size_t)c * 256 + o0 + tx] * lw[c];
        }
        __syncthreads();
#pragma unroll
        for (int s = 0; s < 4; s++) {
            int o = o0 + ty + s * 8;
            size_t rb = (size_t)(seg * 256 + o) * 256;
            Wkv[rb + c0 + tx] = __float2half_rn(t[tx][ty + s * 8]);
        }
    } else if (bid < 512) {
        int o = (bid - 384) * 8 + ty;
        int seg = o >> 8, oo = o & 255;
        int i = seg >> 1, isv = seg & 1;
        const float* W = (isv ? Wv : Wk) + i * 65536;
        const float* b = (isv ? lnvb : lnkb) + i * 256;
        float s = 0.f;
#pragma unroll
        for (int t = 0; t < 8; t++) {
            int c = tx + t * 32;
            s += b[c] * W[(size_t)c * 256 + oo];
        }
#pragma unroll
        for (int off = 16; off; off >>= 1) s += __shfl_xor_sync(0xffffffffu, s, off);
        if (tx == 0) bcat[o] = s;
    } else {
        int local = bid - 512;
        const int prefix[9] = {0, 64, 128, 256, 384, 448, 512, 640, 768};
        int jb = 0;
#pragma unroll
        for (int t = 1; t < 8; t++) if (local >= prefix[t]) jb = t;
        WtJob job = jobs.j[jb];
        int loc = local - prefix[jb];
        int ktiles = job.K >> 5;
        int kt = loc % ktiles, nt = loc / ktiles;
        int k0 = kt * 32, n0 = nt * 32;
        float (*t)[33] = (float (*)[33])tile;
#pragma unroll
        for (int s = 0; s < 4; s++) {
            int k = k0 + ty + s * 8;
            t[ty + s * 8][tx] = job.src[(size_t)k * job.N + n0 + tx];
        }
        __syncthreads();
#pragma unroll
        for (int s = 0; s < 4; s++) {
            int n = n0 + ty + s * 8;
            job.dst[(size_t)n * job.K + k0 + tx] = __float2half_rn(t[tx][ty + s * 8]);
        }
    }
}

// LayerNorm, warp per row; optional fp32 out and/or fp16 out
__global__ __launch_bounds__(256) void ln_kernel(const float* __restrict__ in,
                                                 const float* __restrict__ w,
                                                 const float* __restrict__ b,
                                                 float* __restrict__ outF,
                                                 __half* __restrict__ outH) {
    int wid = threadIdx.x >> 5, lane = threadIdx.x & 31;
    int m = blockIdx.x * 8 + wid;
    const float4* ip = (const float4*)(in + (size_t)m * 256 + lane * 8);
    float4 v0 = ip[0], v1 = ip[1];
    float s = v0.x + v0.y + v0.z + v0.w + v1.x + v1.y + v1.z + v1.w;
#pragma unroll
    for (int o = 16; o; o >>= 1) s += __shfl_xor_sync(0xffffffffu, s, o);
    float mean = s * (1.f / 256.f);
    float x[8] = {v0.x - mean, v0.y - mean, v0.z - mean, v0.w - mean,
                  v1.x - mean, v1.y - mean, v1.z - mean, v1.w - mean};
    float q = 0.f;
#pragma unroll
    for (int e = 0; e < 8; e++) q = fmaf(x[e], x[e], q);
#pragma unroll
    for (int o = 16; o; o >>= 1) q += __shfl_xor_sync(0xffffffffu, q, o);
    float rstd = rsqrtf(q * (1.f / 256.f) + 1e-5f);
    float4 w0 = *(const float4*)(w + lane * 8), w1 = *(const float4*)(w + lane * 8 + 4);
    float4 b0 = *(const float4*)(b + lane * 8), b1 = *(const float4*)(b + lane * 8 + 4);
    float y[8];
    y[0] = x[0] * rstd * w0.x + b0.x; y[1] = x[1] * rstd * w0.y + b0.y;
    y[2] = x[2] * rstd * w0.z + b0.z; y[3] = x[3] * rstd * w0.w + b0.w;
    y[4] = x[4] * rstd * w1.x + b1.x; y[5] = x[5] * rstd * w1.y + b1.y;
    y[6] = x[6] * rstd * w1.z + b1.z; y[7] = x[7] * rstd * w1.w + b1.w;
    if (outF) {
        float4* op = (float4*)(outF + (size_t)m * 256 + lane * 8);
        op[0] = make_float4(y[0], y[1], y[2], y[3]);
        op[1] = make_float4(y[4], y[5], y[6], y[7]);
    }
    if (outH) {
        __half h[8];
#pragma unroll
        for (int e = 0; e < 8; e++) h[e] = __float2half_rn(y[e]);
        *(uint4*)(outH + (size_t)m * 256 + lane * 8) = *(uint4*)h;
    }
}

// fused LN_post + LN_q at block boundary: z3 -> t16 (fp16)
__global__ __launch_bounds__(256) void ln2_kernel(const float* __restrict__ in,
                                                  const float* __restrict__ w1,
                                                  const float* __restrict__ b1,
                                                  const float* __restrict__ w2,
                                                  const float* __restrict__ b2,
                                                  __half* __restrict__ outH) {
    int wid = threadIdx.x >> 5, lane = threadIdx.x & 31;
    int m = blockIdx.x * 8 + wid;
    const float4* ip = (const float4*)(in + (size_t)m * 256 + lane * 8);
    float4 v0 = ip[0], v1 = ip[1];
    float x[8] = {v0.x, v0.y, v0.z, v0.w, v1.x, v1.y, v1.z, v1.w};
    float s = 0.f;
#pragma unroll
    for (int e = 0; e < 8; e++) s += x[e];
#pragma unroll
    for (int o = 16; o; o >>= 1) s += __shfl_xor_sync(0xffffffffu, s, o);
    float mean = s * (1.f / 256.f);
    float q = 0.f;
#pragma unroll
    for (int e = 0; e < 8; e++) { x[e] -= mean; q = fmaf(x[e], x[e], q); }
#pragma unroll
    for (int o = 16; o; o >>= 1) q += __shfl_xor_sync(0xffffffffu, q, o);
    float rstd = rsqrtf(q * (1.f / 256.f) + 1e-5f);
    float4 wA0 = *(const float4*)(w1 + lane * 8), wA1 = *(const float4*)(w1 + lane * 8 + 4);
    float4 bA0 = *(const float4*)(b1 + lane * 8), bA1 = *(const float4*)(b1 + lane * 8 + 4);
    float wa[8] = {wA0.x, wA0.y, wA0.z, wA0.w, wA1.x, wA1.y, wA1.z, wA1.w};
    float ba[8] = {bA0.x, bA0.y, bA0.z, bA0.w, bA1.x, bA1.y, bA1.z, bA1.w};
    float y[8];
#pragma unroll
    for (int e = 0; e < 8; e++) y[e] = x[e] * rstd * wa[e] + ba[e];
    float s2 = 0.f;
#pragma unroll
    for (int e = 0; e < 8; e++) s2 += y[e];
#pragma unroll
    for (int o = 16; o; o >>= 1) s2 += __shfl_xor_sync(0xffffffffu, s2, o);
    float mean2 = s2 * (1.f / 256.f);
    float q2 = 0.f;
#pragma unroll
    for (int e = 0; e < 8; e++) { y[e] -= mean2; q2 = fmaf(y[e], y[e], q2); }
#pragma unroll
    for (int o = 16; o; o >>= 1) q2 += __shfl_xor_sync(0xffffffffu, q2, o);
    float rstd2 = rsqrtf(q2 * (1.f / 256.f) + 1e-5f);
    float4 wB0 = *(const float4*)(w2 + lane * 8), wB1 = *(const float4*)(w2 + lane * 8 + 4);
    float4 bB0 = *(const float4*)(b2 + lane * 8), bB1 = *(const float4*)(b2 + lane * 8 + 4);
    float wb[8] = {wB0.x, wB0.y, wB0.z, wB0.w, wB1.x, wB1.y, wB1.z, wB1.w};
    float bb[8] = {bB0.x, bB0.y, bB0.z, bB0.w, bB1.x, bB1.y, bB1.z, bB1.w};
    __half h[8];
#pragma unroll
    for (int e = 0; e < 8; e++)
        h[e] = __float2half_rn(y[e] * rstd2 * wb[e] + bb[e]);
    *(uint4*)(outH + (size_t)m * 256 + lane * 8) = *(uint4*)h;
}

// fused final: z3 -> LN_post -> L2-normalize -> transposed out (256 x 4096)
__global__ __launch_bounds__(256) void final_kernel(const float* __restrict__ in,
                                                    const float* __restrict__ w,
                                                    const float* __restrict__ b,
                                                    float* __restrict__ out) {
    __shared__ float t[32][257];
    int tid = threadIdx.x;
    int wid = tid >> 5, lane = tid & 31;
    int m0 = blockIdx.x * 32;
#pragma unroll
    for (int r = 0; r < 4; r++) {
        int lr = wid * 4 + r;
        int m = m0 + lr;
        const float4* ip = (const float4*)(in + (size_t)m * 256 + lane * 8);
        float4 v0 = ip[0], v1 = ip[1];
        float x[8] = {v0.x, v0.y, v0.z, v0.w, v1.x, v1.y, v1.z, v1.w};
        float s = 0.f;
#pragma unroll
        for (int e = 0; e < 8; e++) s += x[e];
#pragma unroll
        for (int o = 16; o; o >>= 1) s += __shfl_xor_sync(0xffffffffu, s, o);
        float mean = s * (1.f / 256.f);
        float q = 0.f;
#pragma unroll
        for (int e = 0; e < 8; e++) { x[e] -= mean; q = fmaf(x[e], x[e], q); }
#pragma unroll
        for (int o = 16; o; o >>= 1) q += __shfl_xor_sync(0xffffffffu, q, o);
        float rstd = rsqrtf(q * (1.f / 256.f) + 1e-5f);
        float4 w0 = *(const float4*)(w + lane * 8), w1 = *(const float4*)(w + lane * 8 + 4);
        float4 b0 = *(const float4*)(b + lane * 8), b1 = *(const float4*)(b + lane * 8 + 4);
        float wa[8] = {w0.x, w0.y, w0.z, w0.w, w1.x, w1.y, w1.z, w1.w};
        float ba[8] = {b0.x, b0.y, b0.z, b0.w, b1.x, b1.y, b1.z, b1.w};
        float y[8];
        float q2 = 0.f;
#pragma unroll
        for (int e = 0; e < 8; e++) {
            y[e] = x[e] * rstd * wa[e] + ba[e];
            q2 = fmaf(y[e], y[e], q2);
        }
#pragma unroll
        for (int o = 16; o; o >>= 1) q2 += __shfl_xor_sync(0xffffffffu, q2, o);
        float inv = 1.f / fmaxf(sqrtf(q2), 1e-12f);
#pragma unroll
        for (int e = 0; e < 8; e++) t[lr][lane * 8 + e] = y[e] * inv;
    }
    __syncthreads();
    int tx = tid & 31, ty = tid >> 5;
#pragma unroll
    for (int c0 = 0; c0 < 256; c0 += 8) {
        int c = c0 + ty;
        out[(size_t)c * 4096 + m0 + tx] = t[tx][c];
    }
}

__global__ void transpose_scale(const float* __restrict__ in, float* __restrict__ out,
                                int R, int Cd) {
    __shared__ float t[32][33];
    int bx = blockIdx.x * 32, by = blockIdx.y * 32;
    int x = threadIdx.x, y0 = threadIdx.y;
    for (int yy = y0; yy < 32; yy += 8)
        t[yy][x] = in[(size_t)(by + yy) * Cd + bx + x];
    __syncthreads();
    for (int yy = y0; yy < 32; yy += 8)
        out[(size_t)(bx + yy) * R + by + x] = t[x][yy];
}

// =================== attention: bucketed by w, L1-resident KV ======================
#define BSPLIT 4
__global__ __launch_bounds__(256) void attn_kernel(const float* __restrict__ q,
                                                   const float* __restrict__ KV,
                                                   const int* __restrict__ bcount,
                                                   const int* __restrict__ blist,
                                                   int kvOff,
                                                   __half* __restrict__ a16) {
    int w = blockIdx.x / BSPLIT, part = blockIdx.x % BSPLIT;
    int cnt = bcount[w];
    if (cnt > 128) cnt = 128;
    int h = threadIdx.x >> 5;
    int lane = threadIdx.x & 31;
    int g = lane >> 3, e = lane & 7;
    int base = kvOff + h * 32 + e * 4;
    // KV rows for this bucket (same for all tokens): jL = w, jR = w+1
    for (int idx = part; idx < cnt; idx += BSPLIT) {
        int m = blist[w * 128 + idx];
        float4 qv = *(const float4*)(q + (size_t)m * 256 + h * 32 + e * 4);
        qv.x *= ATTN_SCALE; qv.y *= ATTN_SCALE; qv.z *= ATTN_SCALE; qv.w *= ATTN_SCALE;
        float s[16];
#pragma unroll
        for (int t = 0; t < 16; t++) {
            int n = t * 4 + g;
            int j = ((n & 31) << 7) + ((n < 32) ? w : (w + 1));
            float4 kv = *(const float4*)(KV + (size_t)j * 1024 + base);
            float p = qv.x * kv.x + qv.y * kv.y + qv.z * kv.z + qv.w * kv.w;
            p += __shfl_xor_sync(0xffffffffu, p, 1);
            p += __shfl_xor_sync(0xffffffffu, p, 2);
            p += __shfl_xor_sync(0xffffffffu, p, 4);
            s[t] = p;
        }
        float mx = s[0];
#pragma unroll
        for (int t = 1; t < 16; t++) mx = fmaxf(mx, s[t]);
#pragma unroll
        for (int o = 16; o; o >>= 1) mx = fmaxf(mx, __shfl_xor_sync(0xffffffffu, mx, o));
        float sum = 0.f;
#pragma unroll
        for (int t = 0; t < 16; t++) { s[t] = expf(s[t] - mx); sum += s[t]; }
#pragma unroll
        for (int o = 16; o; o >>= 1) sum += __shfl_xor_sync(0xffffffffu, sum, o);
        float inv = 8.f / sum;
        float4 acc = make_float4(0.f, 0.f, 0.f, 0.f);
#pragma unroll
        for (int t = 0; t < 16; t++) {
            int n = t * 4 + g;
            int j = ((n & 31) << 7) + ((n < 32) ? w : (w + 1));
            float4 v = *(const float4*)(KV + (size_t)j * 1024 + base + 256);
            float p = s[t] * inv;
            acc.x = fmaf(p, v.x, acc.x);
            acc.y = fmaf(p, v.y, acc.y);
            acc.z = fmaf(p, v.z, acc.z);
            acc.w = fmaf(p, v.w, acc.w);
        }
#pragma unroll
        for (int o = 8; o <= 16; o <<= 1) {
            acc.x += __shfl_xor_sync(0xffffffffu, acc.x, o);
            acc.y += __shfl_xor_sync(0xffffffffu, acc.y, o);
            acc.z += __shfl_xor_sync(0xffffffffu, acc.z, o);
            acc.w += __shfl_xor_sync(0xffffffffu, acc.w, o);
        }
        if (g == 0) {
            __half h4[4] = {__float2half_rn(acc.x), __float2half_rn(acc.y),
                            __float2half_rn(acc.z), __float2half_rn(acc.w)};
            *(uint2*)(a16 + (size_t)m * 256 + h * 32 + e * 4) = *(uint2*)h4;
        }
    }
}

// =================== mma.sync fp16 GEMM: 128x64 tile, 3-stage =====================
#define ASTRIDE 80
#define STAGE_BYTES 15360
#define NSTAGE 3
template <int EPI>
__global__ __launch_bounds__(256, 2) void mma_gemm(const __half* __restrict__ A,
                                                   const __half* __restrict__ B,
                                                   const float* __restrict__ bias,
                                                   const float* __restrict__ resid,
                                                   float* __restrict__ Cf,
                                                   __half* __restrict__ Ch,
                                                   int Krow, int N) {
    __shared__ __align__(16) char sm[NSTAGE * STAGE_BYTES];
    uint32_t smBase = smem_u32(sm);
    int tid = threadIdx.x;
    int wid = tid >> 5, lane = tid & 31;
    int wm = wid >> 1, wn = wid & 1;
    int m0 = blockIdx.y << 7, n0 = blockIdx.x << 6;
    int niter = Krow >> 5;

    float acc[2][4][4];
#pragma unroll
    for (int t = 0; t < 2; t++)
#pragma unroll
        for (int j = 0; j < 4; j++)
#pragma unroll
            for (int e = 0; e < 4; e++) acc[t][j][e] = 0.f;

    int arow = tid >> 2, ach = tid & 3;
    const __half* gA0 = A + (size_t)m0 * Krow;
    const __half* gB0 = B + (size_t)(n0 + arow) * Krow + (ach << 3);

    uint32_t aOff = (uint32_t)((wm * 32 + (lane & 15)) * ASTRIDE + ((lane >> 4) << 4));
    uint32_t bOff = (uint32_t)((wn * 32 + (lane & 7) + ((lane >> 4) << 3)) * ASTRIDE +
                               (((lane >> 3) & 1) << 4));

#pragma unroll
    for (int st = 0; st < NSTAGE - 1; st++) {
        uint32_t sA = smBase + st * STAGE_BYTES;
        int k0 = st << 5;
#pragma unroll
        for (int i = 0; i < 2; i++) {
            int u = tid + (i << 8);
            int row = u >> 2, ch = u & 3;
            cp16(sA + row * ASTRIDE + ch * 16, gA0 + (size_t)row * Krow + k0 + (ch << 3));
        }
        cp16(sA + 10240 + arow * ASTRIDE + ach * 16, gB0 + k0);
        cp_commit();
    }

    int stC = 0, stP = NSTAGE - 1;
    for (int it = 0; it < niter; ++it) {
        cp_wait1();
        __syncthreads();
        if (it + NSTAGE - 1 < niter) {
            int k0 = (it + NSTAGE - 1) << 5;
            uint32_t sA = smBase + stP * STAGE_BYTES;
#pragma unroll
            for (int i = 0; i < 2; i++) {
                int u = tid + (i << 8);
                int row = u >> 2, ch = u & 3;
                cp16(sA + row * ASTRIDE + ch * 16, gA0 + (size_t)row * Krow + k0 + (ch << 3));
            }
            cp16(sA + 10240 + arow * ASTRIDE + ach * 16, gB0 + k0);
        }
        cp_commit();
        if (++stP == NSTAGE) stP = 0;

        uint32_t aBase = smBase + stC * STAGE_BYTES + aOff;
        uint32_t bBase = smBase + stC * STAGE_BYTES + 10240 + bOff;
        if (++stC == NSTAGE) stC = 0;
#pragma unroll
        for (int ks = 0; ks < 2; ks++) {
            uint32_t a[2][4], b[2][4];
            ldsm4(a[0], aBase + ks * 32);
            ldsm4(a[1], aBase + 16 * ASTRIDE + ks * 32);
            ldsm4(b[0], bBase + ks * 32);
            ldsm4(b[1], bBase + 16 * ASTRIDE + ks * 32);
#pragma unroll
            for (int t = 0; t < 2; t++) {
#pragma unroll
                for (int j = 0; j < 4; j++) {
                    uint32_t b0 = b[j >> 1][(j & 1) ? 2 : 0];
                    uint32_t b1 = b[j >> 1][(j & 1) ? 3 : 1];
                    mma16816(acc[t][j], a[t], b0, b1);
                }
            }
        }
    }

#pragma unroll
    for (int t = 0; t < 2; t++) {
        int row0 = m0 + wm * 32 + t * 16 + (lane >> 2);
        int row1 = row0 + 8;
#pragma unroll
        for (int j = 0; j < 4; j++) {
            int col = n0 + wn * 32 + j * 8 + ((lane & 3) << 1);
            float v0 = acc[t][j][0], v1 = acc[t][j][1];
            float v2 = acc[t][j][2], v3 = acc[t][j][3];
            if (EPI != 0 || bias) {
                float b0 = bias[col], b1 = bias[col + 1];
                v0 += b0; v1 += b1; v2 += b0; v3 += b1;
            }
            if (EPI == 1) {
                v0 = 0.5f * v0 * (1.f + erff(v0 * 0.70710678118654752f));
                v1 = 0.5f * v1 * (1.f + erff(v1 * 0.70710678118654752f));
                v2 = 0.5f * v2 * (1.f + erff(v2 * 0.70710678118654752f));
                v3 = 0.5f * v3 * (1.f + erff(v3 * 0.70710678118654752f));
                *(__half2*)(Ch + (size_t)row0 * N + col) =
                    __halves2half2(__float2half_rn(v0), __float2half_rn(v1));
                *(__half2*)(Ch + (size_t)row1 * N + col) =
                    __halves2half2(__float2half_rn(v2), __float2half_rn(v3));
            } else {
                if (EPI == 2) {
                    float2 r0 = *(const float2*)(resid + (size_t)row0 * N + col);
                    float2 r1 = *(const float2*)(resid + (size_t)row1 * N + col);
                    v0 += r0.x; v1 += r0.y; v2 += r1.x; v3 += r1.y;
                }
                *(float2*)(Cf + (size_t)row0 * N + col) = make_float2(v0, v1);
                *(float2*)(Cf + (size_t)row1 * N + col) = make_float2(v2, v3);
            }
        }
    }
}

// =================== 64x64-tile variant (for N=256 GEMMs) ==========================
#define STAGE64 10240
template <int EPI>
__global__ __launch_bounds__(256, 3) void mma_gemm64(const __half* __restrict__ A,
                                                     const __half* __restrict__ B,
                                                     const float* __restrict__ bias,
                                                     const float* __restrict__ resid,
                                                     float* __restrict__ Cf,
                                                     int Krow, int N) {
    __shared__ __align__(16) char sm[NSTAGE * STAGE64];
    uint32_t smBase = smem_u32(sm);
    int tid = threadIdx.x;
    int wid = tid >> 5, lane = tid & 31;
    int wm = wid >> 1, wn = wid & 1;
    int m0 = blockIdx.y << 6, n0 = blockIdx.x << 6;
    int niter = Krow >> 5;

    float acc[4][4];
#pragma unroll
    for (int j = 0; j < 4; j++)
#pragma unroll
        for (int e = 0; e < 4; e++) acc[j][e] = 0.f;

    int arow = tid >> 2, ach = tid & 3;
    const __half* gA0 = A + (size_t)(m0 + arow) * Krow + (ach << 3);
    const __half* gB0 = B + (size_t)(n0 + arow) * Krow + (ach << 3);
    uint32_t sOff = arow * ASTRIDE + (ach << 4);

    uint32_t aOff = (uint32_t)((wm * 16 + (lane & 15)) * ASTRIDE + ((lane >> 4) << 4));
    uint32_t bOff = (uint32_t)(5120 + (wn * 32 + (lane & 7) + ((lane >> 4) << 3)) * ASTRIDE +
                               (((lane >> 3) & 1) << 4));

#pragma unroll
    for (int st = 0; st < NSTAGE - 1; st++) {
        uint32_t sA = smBase + st * STAGE64;
        int k0 = st << 5;
        cp16(sA + sOff, gA0 + k0);
        cp16(sA + 5120 + sOff, gB0 + k0);
        cp_commit();
    }

    int stC = 0, stP = NSTAGE - 1;
    for (int it = 0; it < niter; ++it) {
        cp_wait1();
        __syncthreads();
        if (it + NSTAGE - 1 < niter) {
            int k0 = (it + NSTAGE - 1) << 5;
            uint32_t sA = smBase + stP * STAGE64;
            cp16(sA + sOff, gA0 + k0);
            cp16(sA + 5120 + sOff, gB0 + k0);
        }
        cp_commit();
        if (++stP == NSTAGE) stP = 0;

        uint32_t aBase = smBase + stC * STAGE64 + aOff;
        uint32_t bBase = smBase + stC * STAGE64 + bOff;
        if (++stC == NSTAGE) stC = 0;
#pragma unroll
        for (int ks = 0; ks < 2; ks++) {
            uint32_t a[4], b[2][4];
            ldsm4(a, aBase + ks * 32);
            ldsm4(b[0], bBase + ks * 32);
            ldsm4(b[1], bBase + 16 * ASTRIDE + ks * 32);
#pragma unroll
            for (int j = 0; j < 4; j++) {
                uint32_t b0 = b[j >> 1][(j & 1) ? 2 : 0];
                uint32_t b1 = b[j >> 1][(j & 1) ? 3 : 1];
                mma16816(acc[j], a, b0, b1);
            }
        }
    }

    int row0 = m0 + wm * 16 + (lane >> 2);
    int row1 = row0 + 8;
#pragma unroll
    for (int j = 0; j < 4; j++) {
        int col = n0 + wn * 32 + j * 8 + ((lane & 3) << 1);
        float v0 = acc[j][0], v1 = acc[j][1], v2 = acc[j][2], v3 = acc[j][3];
        if (bias) {
            float b0 = bias[col], b1 = bias[col + 1];
            v0 += b0; v1 += b1; v2 += b0; v3 += b1;
        }
        if (EPI == 2) {
            float2 r0 = *(const float2*)(resid + (size_t)row0 * N + col);
            float2 r1 = *(const float2*)(resid + (size_t)row1 * N + col);
            v0 += r0.x; v1 += r0.y; v2 += r1.x; v3 += r1.y;
        }
        *(float2*)(Cf + (size_t)row0 * N + col) = make_float2(v0, v1);
        *(float2*)(Cf + (size_t)row1 * N + col) = make_float2(v2, v3);
    }
}

// =================== host launch ===================
extern "C" void kernel_launch(void* const* d_in, const int* in_sizes, int n_in,
                              void* d_out, int out_size) {
    (void)in_sizes; (void)n_in; (void)out_size;
    const float* grd2sat = (const float*)d_in[0];
    const float* grd_x   = (const float*)d_in[1];
    const float* u       = (const float*)d_in[2];
    const float* ln_q_w  = (const float*)d_in[3];
    const float* ln_q_b  = (const float*)d_in[4];
    const float* ln_k_w  = (const float*)d_in[5];
    const float* ln_k_b  = (const float*)d_in[6];
    const float* ln_v_w  = (const float*)d_in[7];
    const float* ln_v_b  = (const float*)d_in[8];
    const float* Wq      = (const float*)d_in[9];
    const float* Wk      = (const float*)d_in[10];
    const float* Wv      = (const float*)d_in[11];
    const float* Wproj   = (const float*)d_in[12];
    const float* bproj   = (const float*)d_in[13];
    const float* ln_pre_w  = (const float*)d_in[14];
    const float* ln_pre_b  = (const float*)d_in[15];
    const float* Wm1     = (const float*)d_in[16];
    const float* bm1     = (const float*)d_in[17];
    const float* Wm2     = (const float*)d_in[18];
    const float* bm2     = (const float*)d_in[19];
    const float* ln_post_w = (const float*)d_in[20];
    const float* ln_post_b = (const float*)d_in[21];
    float* out = (float*)d_out;

    __half *Xn, *Wkv, *t16, *a16, *z216, *h16, *Wq2, *Wp2, *Wm1c, *Wm2c;
    float *bcat, *KV, *x, *q, *z1, *z2, *z3;
    int *bcount, *blist;
    cudaGetSymbolAddress((void**)&Xn, g_Xn);
    cudaGetSymbolAddress((void**)&Wkv, g_Wkv);
    cudaGetSymbolAddress((void**)&bcat, g_bcat);
    cudaGetSymbolAddress((void**)&KV, g_KV);
    cudaGetSymbolAddress((void**)&x, g_x);
    cudaGetSymbolAddress((void**)&t16, g_t16);
    cudaGetSymbolAddress((void**)&q, g_q);
    cudaGetSymbolAddress((void**)&a16, g_a16);
    cudaGetSymbolAddress((void**)&z1, g_z1);
    cudaGetSymbolAddress((void**)&z2, g_z2);
    cudaGetSymbolAddress((void**)&z216, g_z216);
    cudaGetSymbolAddress((void**)&h16, g_h16);
    cudaGetSymbolAddress((void**)&z3, g_z3);
    cudaGetSymbolAddress((void**)&Wq2, g_Wq2);
    cudaGetSymbolAddress((void**)&Wp2, g_Wp2);
    cudaGetSymbolAddress((void**)&Wm1c, g_Wm1c);
    cudaGetSymbolAddress((void**)&Wm2c, g_Wm2c);
    cudaGetSymbolAddress((void**)&bcount, g_bcount);
    cudaGetSymbolAddress((void**)&blist, g_blist);

    WtJobs jobs;
    for (int i = 0; i < 2; i++) {
        jobs.j[i * 4 + 0] = {Wq + i * 65536, Wq2 + i * 256 * 256, 256, 256};
        jobs.j[i * 4 + 1] = {Wproj + i * 65536, Wp2 + i * 256 * 256, 256, 256};
        jobs.j[i * 4 + 2] = {Wm1 + i * 131072, Wm1c + i * 512 * 256, 256, 512};
        jobs.j[i * 4 + 3] = {Wm2 + i * 131072, Wm2c + i * 256 * 512, 512, 256};
    }

    // ---- prep ----
    bucket_zero<<<1, 128>>>(bcount);
    bucket_kernel<<<16, 256>>>(u, bcount, blist);
    prep_kernel<<<1280, 256>>>(grd_x, Wk, Wv, ln_k_w, ln_v_w, ln_k_b, ln_v_b,
                               Xn, Wkv, bcat, jobs);

    // KV = Xn @ Wkv + bcat : (4096 x 1024)
    mma_gemm<0><<<dim3(16, 32), 256>>>(Xn, Wkv, bcat, nullptr, KV, nullptr, 256, 1024);
    transpose_scale<<<dim3(128, 8), dim3(32, 8)>>>(grd2sat, x, 256, 4096);

    for (int i = 0; i < 2; i++) {
        if (i == 0)
            ln_kernel<<<512, 256>>>(x, ln_q_w, ln_q_b, nullptr, t16);
        mma_gemm64<0><<<dim3(4, 64), 256>>>(t16, Wq2 + i * 256 * 256, nullptr, nullptr, q,
                                            256, 256);
        attn_kernel<<<127 * BSPLIT, 256>>>(q, KV, bcount, blist, i * 512, a16);
        mma_gemm64<0><<<dim3(4, 64), 256>>>(a16, Wp2 + i * 256 * 256, bproj + i * 256,
                                            nullptr, z1, 256, 256);
        ln_kernel<<<512, 256>>>(z1, ln_pre_w + i * 256, ln_pre_b + i * 256, z2, z216);
        mma_gemm<1><<<dim3(8, 32), 256>>>(z216, Wm1c + i * 512 * 256, bm1 + i * 512,
                                          nullptr, nullptr, h16, 256, 512);
        mma_gemm64<2><<<dim3(4, 64), 256>>>(h16, Wm2c + i * 256 * 512, bm2 + i * 256, z2,
                                            z3, 512, 256);
        if (i == 0)
            ln2_kernel<<<512, 256>>>(z3, ln_post_w, ln_post_b, ln_q_w + 256, ln_q_b + 256,
                                     t16);
    }

    final_kernel<<<128, 256>>>(z3, ln_post_w + 256, ln_post_b + 256, out);
}

// round 14
// speedup vs baseline: 1.2527x; 1.2527x over previous
#include <cuda_runtime.h>
#include <cuda_fp16.h>
#include <math.h>
#include <stdint.h>

#define ATTN_SCALE 0.17677669529663687f  // 32^-0.5

__device__ __forceinline__ uint32_t smem_u32(const void* p) {
    uint32_t a;
    asm("{ .reg .u64 t; cvta.to.shared.u64 t, %1; cvt.u32.u64 %0, t; }" : "=r"(a) : "l"(p));
    return a;
}
__device__ __forceinline__ void cp16(uint32_t s, const void* g) {
    asm volatile("cp.async.cg.shared.global [%0], [%1], 16;" :: "r"(s), "l"(g));
}
__device__ __forceinline__ void cp_commit() { asm volatile("cp.async.commit_group;"); }
__device__ __forceinline__ void cp_wait1() { asm volatile("cp.async.wait_group 1;"); }
__device__ __forceinline__ void ldsm4(uint32_t r[4], uint32_t addr) {
    asm volatile("ldmatrix.sync.aligned.m8n8.x4.shared.b16 {%0,%1,%2,%3}, [%4];"
                 : "=r"(r[0]), "=r"(r[1]), "=r"(r[2]), "=r"(r[3]) : "r"(addr));
}
__device__ __forceinline__ void mma16816(float c[4], const uint32_t a[4], uint32_t b0,
                                         uint32_t b1) {
    asm volatile(
        "mma.sync.aligned.m16n8k16.row.col.f32.f16.f16.f32 "
        "{%0,%1,%2,%3}, {%4,%5,%6,%7}, {%8,%9}, {%0,%1,%2,%3};"
        : "+f"(c[0]), "+f"(c[1]), "+f"(c[2]), "+f"(c[3])
        : "r"(a[0]), "r"(a[1]), "r"(a[2]), "r"(a[3]), "r"(b0), "r"(b1));
}

// =================== device scratch ===================
__device__ __half g_Xn[4096 * 256];
__device__ __half g_Wkv[1024 * 256];
__device__ float g_bcat[1024];
__device__ __half g_KVh[4096 * 1024];
__device__ float g_x[4096 * 256];
__device__ __half g_t16[4096 * 256];
__device__ float g_q[4096 * 256];
__device__ __half g_a16[4096 * 256];
__device__ float g_z1[4096 * 256];
__device__ float g_z2[4096 * 256];
__device__ __half g_z216[4096 * 256];
__device__ __half g_h16[4096 * 512];
__device__ float g_z3[4096 * 256];
__device__ __half g_Wq2[2 * 256 * 256];
__device__ __half g_Wp2[2 * 256 * 256];
__device__ __half g_Wm1c[2 * 512 * 256];
__device__ __half g_Wm2c[2 * 256 * 512];

// =================== fused prep kernel (R11) ===================
struct WtJob { const float* src; __half* dst; int K; int N; };
struct WtJobs { WtJob j[8]; };
__global__ __launch_bounds__(256) void prep_kernel(
    const float* __restrict__ grd_x,
    const float* __restrict__ Wk, const float* __restrict__ Wv,
    const float* __restrict__ lnkw, const float* __restrict__ lnvw,
    const float* __restrict__ lnkb, const float* __restrict__ lnvb,
    __half* __restrict__ Xn, __half* __restrict__ Wkv, float* __restrict__ bcat,
    WtJobs jobs) {
    __shared__ float tile[256][33];
    __shared__ float ps[8][32], pq[8][32];
    __shared__ float cmu[32], crs[32];
    int bid = blockIdx.x;
    int tid = threadIdx.x;
    int tx = tid & 31, ty = tid >> 5;

    if (bid < 128) {
        int j0 = bid * 32;
        float s = 0.f, q = 0.f;
#pragma unroll
        for (int t = 0; t < 32; t++) {
            int c = t * 8 + ty;
            float v = grd_x[(size_t)c * 4096 + j0 + tx];
            tile[c][tx] = v;
            s += v; q += v * v;
        }
        ps[ty][tx] = s; pq[ty][tx] = q;
        __syncthreads();
        if (ty == 0) {
            float ss = 0.f, qq = 0.f;
#pragma unroll
            for (int r = 0; r < 8; r++) { ss += ps[r][tx]; qq += pq[r][tx]; }
            float mu = ss * (1.f / 256.f);
            cmu[tx] = mu;
            crs[tx] = rsqrtf(qq * (1.f / 256.f) - mu * mu + 1e-5f);
        }
        __syncthreads();
#pragma unroll
        for (int r = 0; r < 4; r++) {
            int jj = ty * 4 + r;
            float mu = cmu[jj], rs = crs[jj];
            size_t rb = (size_t)(j0 + jj) * 256 + tx * 8;
            __half h[8];
#pragma unroll
            for (int e = 0; e < 8; e++)
                h[e] = __float2half_rn((tile[tx * 8 + e][jj] - mu) * rs);
            *(uint4*)(Xn + rb) = *(uint4*)h;
        }
    } else if (bid < 384) {
        int local = bid - 128;
        int ct = local & 7, ot = (local >> 3) & 7, seg = local >> 6;
        int i = seg >> 1, isv = seg & 1;
        const float* W = (isv ? Wv : Wk) + i * 65536;
        const float* lw = (isv ? lnvw : lnkw) + i * 256;
        int c0 = ct * 32, o0 = ot * 32;
        float (*t)[33] = (float (*)[33])tile;
#pragma unroll
        for (int s = 0; s < 4; s++) {
            int c = c0 + ty + s * 8;
            t[ty + s * 8][tx] = W[(size_t)c * 256 + o0 + tx] * lw[c];
        }
        __syncthreads();
#pragma unroll
        for (int s = 0; s < 4; s++) {
            int o = o0 + ty + s * 8;
            size_t rb = (size_t)(seg * 256 + o) * 256;
            Wkv[rb + c0 + tx] = __float2half_rn(t[tx][ty + s * 8]);
        }
    } else if (bid < 512) {
        int o = (bid - 384) * 8 + ty;
        int seg = o >> 8, oo = o & 255;
        int i = seg >> 1, isv = seg & 1;
        const float* W = (isv ? Wv : Wk) + i * 65536;
        const float* b = (isv ? lnvb : lnkb) + i * 256;
        float s = 0.f;
#pragma unroll
        for (int t = 0; t < 8; t++) {
            int c = tx + t * 32;
            s += b[c] * W[(size_t)c * 256 + oo];
        }
#pragma unroll
        for (int off = 16; off; off >>= 1) s += __shfl_xor_sync(0xffffffffu, s, off);
        if (tx == 0) bcat[o] = s;
    } else {
        int local = bid - 512;
        const int prefix[9] = {0, 64, 128, 256, 384, 448, 512, 640, 768};
        int jb = 0;
#pragma unroll
        for (int t = 1; t < 8; t++) if (local >= prefix[t]) jb = t;
        WtJob job = jobs.j[jb];
        int loc = local - prefix[jb];
        int ktiles = job.K >> 5;
        int kt = loc % ktiles, nt = loc / ktiles;
        int k0 = kt * 32, n0 = nt * 32;
        float (*t)[33] = (float (*)[33])tile;
#pragma unroll
        for (int s = 0; s < 4; s++) {
            int k = k0 + ty + s * 8;
            t[ty + s * 8][tx] = job.src[(size_t)k * job.N + n0 + tx];
        }
        __syncthreads();
#pragma unroll
        for (int s = 0; s < 4; s++) {
            int n = n0 + ty + s * 8;
            job.dst[(size_t)n * job.K + k0 + tx] = __float2half_rn(t[tx][ty + s * 8]);
        }
    }
}

// LayerNorm, warp per row; optional fp32 out and/or fp16 out
__global__ __launch_bounds__(256) void ln_kernel(const float* __restrict__ in,
                                                 const float* __restrict__ w,
                                                 const float* __restrict__ b,
                                                 float* __restrict__ outF,
                                                 __half* __restrict__ outH) {
    int wid = threadIdx.x >> 5, lane = threadIdx.x & 31;
    int m = blockIdx.x * 8 + wid;
    const float4* ip = (const float4*)(in + (size_t)m * 256 + lane * 8);
    float4 v0 = ip[0], v1 = ip[1];
    float s = v0.x + v0.y + v0.z + v0.w + v1.x + v1.y + v1.z + v1.w;
#pragma unroll
    for (int o = 16; o; o >>= 1) s += __shfl_xor_sync(0xffffffffu, s, o);
    float mean = s * (1.f / 256.f);
    float x[8] = {v0.x - mean, v0.y - mean, v0.z - mean, v0.w - mean,
                  v1.x - mean, v1.y - mean, v1.z - mean, v1.w - mean};
    float q = 0.f;
#pragma unroll
    for (int e = 0; e < 8; e++) q = fmaf(x[e], x[e], q);
#pragma unroll
    for (int o = 16; o; o >>= 1) q += __shfl_xor_sync(0xffffffffu, q, o);
    float rstd = rsqrtf(q * (1.f / 256.f) + 1e-5f);
    float4 w0 = *(const float4*)(w + lane * 8), w1 = *(const float4*)(w + lane * 8 + 4);
    float4 b0 = *(const float4*)(b + lane * 8), b1 = *(const float4*)(b + lane * 8 + 4);
    float y[8];
    y[0] = x[0] * rstd * w0.x + b0.x; y[1] = x[1] * rstd * w0.y + b0.y;
    y[2] = x[2] * rstd * w0.z + b0.z; y[3] = x[3] * rstd * w0.w + b0.w;
    y[4] = x[4] * rstd * w1.x + b1.x; y[5] = x[5] * rstd * w1.y + b1.y;
    y[6] = x[6] * rstd * w1.z + b1.z; y[7] = x[7] * rstd * w1.w + b1.w;
    if (outF) {
        float4* op = (float4*)(outF + (size_t)m * 256 + lane * 8);
        op[0] = make_float4(y[0], y[1], y[2], y[3]);
        op[1] = make_float4(y[4], y[5], y[6], y[7]);
    }
    if (outH) {
        __half h[8];
#pragma unroll
        for (int e = 0; e < 8; e++) h[e] = __float2half_rn(y[e]);
        *(uint4*)(outH + (size_t)m * 256 + lane * 8) = *(uint4*)h;
    }
}

// fused LN_post + LN_q at block boundary: z3 -> t16 (fp16)
__global__ __launch_bounds__(256) void ln2_kernel(const float* __restrict__ in,
                                                  const float* __restrict__ w1,
                                                  const float* __restrict__ b1,
                                                  const float* __restrict__ w2,
                                                  const float* __restrict__ b2,
                                                  __half* __restrict__ outH) {
    int wid = threadIdx.x >> 5, lane = threadIdx.x & 31;
    int m = blockIdx.x * 8 + wid;
    const float4* ip = (const float4*)(in + (size_t)m * 256 + lane * 8);
    float4 v0 = ip[0], v1 = ip[1];
    float x[8] = {v0.x, v0.y, v0.z, v0.w, v1.x, v1.y, v1.z, v1.w};
    float s = 0.f;
#pragma unroll
    for (int e = 0; e < 8; e++) s += x[e];
#pragma unroll
    for (int o = 16; o; o >>= 1) s += __shfl_xor_sync(0xffffffffu, s, o);
    float mean = s * (1.f / 256.f);
    float q = 0.f;
#pragma unroll
    for (int e = 0; e < 8; e++) { x[e] -= mean; q = fmaf(x[e], x[e], q); }
#pragma unroll
    for (int o = 16; o; o >>= 1) q += __shfl_xor_sync(0xffffffffu, q, o);
    float rstd = rsqrtf(q * (1.f / 256.f) + 1e-5f);
    float4 wA0 = *(const float4*)(w1 + lane * 8), wA1 = *(const float4*)(w1 + lane * 8 + 4);
    float4 bA0 = *(const float4*)(b1 + lane * 8), bA1 = *(const float4*)(b1 + lane * 8 + 4);
    float wa[8] = {wA0.x, wA0.y, wA0.z, wA0.w, wA1.x, wA1.y, wA1.z, wA1.w};
    float ba[8] = {bA0.x, bA0.y, bA0.z, bA0.w, bA1.x, bA1.y, bA1.z, bA1.w};
    float y[8];
#pragma unroll
    for (int e = 0; e < 8; e++) y[e] = x[e] * rstd * wa[e] + ba[e];
    float s2 = 0.f;
#pragma unroll
    for (int e = 0; e < 8; e++) s2 += y[e];
#pragma unroll
    for (int o = 16; o; o >>= 1) s2 += __shfl_xor_sync(0xffffffffu, s2, o);
    float mean2 = s2 * (1.f / 256.f);
    float q2 = 0.f;
#pragma unroll
    for (int e = 0; e < 8; e++) { y[e] -= mean2; q2 = fmaf(y[e], y[e], q2); }
#pragma unroll
    for (int o = 16; o; o >>= 1) q2 += __shfl_xor_sync(0xffffffffu, q2, o);
    float rstd2 = rsqrtf(q2 * (1.f / 256.f) + 1e-5f);
    float4 wB0 = *(const float4*)(w2 + lane * 8), wB1 = *(const float4*)(w2 + lane * 8 + 4);
    float4 bB0 = *(const float4*)(b2 + lane * 8), bB1 = *(const float4*)(b2 + lane * 8 + 4);
    float wb[8] = {wB0.x, wB0.y, wB0.z, wB0.w, wB1.x, wB1.y, wB1.z, wB1.w};
    float bb[8] = {bB0.x, bB0.y, bB0.z, bB0.w, bB1.x, bB1.y, bB1.z, bB1.w};
    __half h[8];
#pragma unroll
    for (int e = 0; e < 8; e++)
        h[e] = __float2half_rn(y[e] * rstd2 * wb[e] + bb[e]);
    *(uint4*)(outH + (size_t)m * 256 + lane * 8) = *(uint4*)h;
}

// fused final: z3 -> LN_post -> L2-normalize -> transposed out (256 x 4096)
__global__ __launch_bounds__(256) void final_kernel(const float* __restrict__ in,
                                                    const float* __restrict__ w,
                                                    const float* __restrict__ b,
                                                    float* __restrict__ out) {
    __shared__ float t[32][257];
    int tid = threadIdx.x;
    int wid = tid >> 5, lane = tid & 31;
    int m0 = blockIdx.x * 32;
#pragma unroll
    for (int r = 0; r < 4; r++) {
        int lr = wid * 4 + r;
        int m = m0 + lr;
        const float4* ip = (const float4*)(in + (size_t)m * 256 + lane * 8);
        float4 v0 = ip[0], v1 = ip[1];
        float x[8] = {v0.x, v0.y, v0.z, v0.w, v1.x, v1.y, v1.z, v1.w};
        float s = 0.f;
#pragma unroll
        for (int e = 0; e < 8; e++) s += x[e];
#pragma unroll
        for (int o = 16; o; o >>= 1) s += __shfl_xor_sync(0xffffffffu, s, o);
        float mean = s * (1.f / 256.f);
        float q = 0.f;
#pragma unroll
        for (int e = 0; e < 8; e++) { x[e] -= mean; q = fmaf(x[e], x[e], q); }
#pragma unroll
        for (int o = 16; o; o >>= 1) q += __shfl_xor_sync(0xffffffffu, q, o);
        float rstd = rsqrtf(q * (1.f / 256.f) + 1e-5f);
        float4 w0 = *(const float4*)(w + lane * 8), w1 = *(const float4*)(w + lane * 8 + 4);
        float4 b0 = *(const float4*)(b + lane * 8), b1 = *(const float4*)(b + lane * 8 + 4);
        float wa[8] = {w0.x, w0.y, w0.z, w0.w, w1.x, w1.y, w1.z, w1.w};
        float ba[8] = {b0.x, b0.y, b0.z, b0.w, b1.x, b1.y, b1.z, b1.w};
        float y[8];
        float q2 = 0.f;
#pragma unroll
        for (int e = 0; e < 8; e++) {
            y[e] = x[e] * rstd * wa[e] + ba[e];
            q2 = fmaf(y[e], y[e], q2);
        }
#pragma unroll
        for (int o = 16; o; o >>= 1) q2 += __shfl_xor_sync(0xffffffffu, q2, o);
        float inv = 1.f / fmaxf(sqrtf(q2), 1e-12f);
#pragma unroll
        for (int e = 0; e < 8; e++) t[lr][lane * 8 + e] = y[e] * inv;
    }
    __syncthreads();
    int tx = tid & 31, ty = tid >> 5;
#pragma unroll
    for (int c0 = 0; c0 < 256; c0 += 8) {
        int c = c0 + ty;
        out[(size_t)c * 4096 + m0 + tx] = t[tx][c];
    }
}

__global__ void transpose_scale(const float* __restrict__ in, float* __restrict__ out,
                                int R, int Cd) {
    __shared__ float t[32][33];
    int bx = blockIdx.x * 32, by = blockIdx.y * 32;
    int x = threadIdx.x, y0 = threadIdx.y;
    for (int yy = y0; yy < 32; yy += 8)
        t[yy][x] = in[(size_t)(by + yy) * Cd + bx + x];
    __syncthreads();
    for (int yy = y0; yy < 32; yy += 8)
        out[(size_t)(bx + yy) * R + by + x] = t[x][yy];
}

// =================== attention: R10 layout, fp16 KV ================================
__global__ __launch_bounds__(256) void attn_kernel(const float* __restrict__ q,
                                                   const __half* __restrict__ KVh,
                                                   const float* __restrict__ u,
                                                   int kvOff,
                                                   __half* __restrict__ a16) {
    int m = blockIdx.x;
    int h = threadIdx.x >> 5;
    int lane = threadIdx.x & 31;
    int g = lane >> 3, e = lane & 7;
    float uf = floorf(u[m]);
    int jL = (int)fminf(fmaxf(uf, 0.f), 127.f);
    int jR = (int)fminf(fmaxf(uf + 1.f, 0.f), 127.f);
    int base = kvOff + h * 32 + e * 4;
    float4 qv = *(const float4*)(q + (size_t)m * 256 + h * 32 + e * 4);
    qv.x *= ATTN_SCALE; qv.y *= ATTN_SCALE; qv.z *= ATTN_SCALE; qv.w *= ATTN_SCALE;

    float s[16];
#pragma unroll
    for (int t = 0; t < 16; t++) {
        int n = t * 4 + g;
        int j = ((n & 31) << 7) + ((n < 32) ? jL : jR);
        uint2 raw = *(const uint2*)(KVh + (size_t)j * 1024 + base);
        float2 f01 = __half22float2(*(const __half2*)&raw.x);
        float2 f23 = __half22float2(*(const __half2*)&raw.y);
        float p = qv.x * f01.x + qv.y * f01.y + qv.z * f23.x + qv.w * f23.y;
        p += __shfl_xor_sync(0xffffffffu, p, 1);
        p += __shfl_xor_sync(0xffffffffu, p, 2);
        p += __shfl_xor_sync(0xffffffffu, p, 4);
        s[t] = p;
    }
    float mx = s[0];
#pragma unroll
    for (int t = 1; t < 16; t++) mx = fmaxf(mx, s[t]);
#pragma unroll
    for (int o = 16; o; o >>= 1) mx = fmaxf(mx, __shfl_xor_sync(0xffffffffu, mx, o));
    float sum = 0.f;
#pragma unroll
    for (int t = 0; t < 16; t++) { s[t] = expf(s[t] - mx); sum += s[t]; }
#pragma unroll
    for (int o = 16; o; o >>= 1) sum += __shfl_xor_sync(0xffffffffu, sum, o);
    float inv = 8.f / sum;

    float4 acc = make_float4(0.f, 0.f, 0.f, 0.f);
#pragma unroll
    for (int t = 0; t < 16; t++) {
        int n = t * 4 + g;
        int j = ((n & 31) << 7) + ((n < 32) ? jL : jR);
        uint2 raw = *(const uint2*)(KVh + (size_t)j * 1024 + base + 256);
        float2 f01 = __half22float2(*(const __half2*)&raw.x);
        float2 f23 = __half22float2(*(const __half2*)&raw.y);
        float p = s[t] * inv;
        acc.x = fmaf(p, f01.x, acc.x);
        acc.y = fmaf(p, f01.y, acc.y);
        acc.z = fmaf(p, f23.x, acc.z);
        acc.w = fmaf(p, f23.y, acc.w);
    }
#pragma unroll
    for (int o = 8; o <= 16; o <<= 1) {
        acc.x += __shfl_xor_sync(0xffffffffu, acc.x, o);
        acc.y += __shfl_xor_sync(0xffffffffu, acc.y, o);
        acc.z += __shfl_xor_sync(0xffffffffu, acc.z, o);
        acc.w += __shfl_xor_sync(0xffffffffu, acc.w, o);
    }
    if (g == 0) {
        __half h4[4] = {__float2half_rn(acc.x), __float2half_rn(acc.y),
                        __float2half_rn(acc.z), __float2half_rn(acc.w)};
        *(uint2*)(a16 + (size_t)m * 256 + h * 32 + e * 4) = *(uint2*)h4;
    }
}

// =================== mma.sync fp16 GEMM: 128x64 tile, 3-stage =====================
// EPI 0: Cf = acc (+bias)  EPI 1: Ch = f16(gelu(acc+bias))  EPI 2: Cf = acc+bias+resid
// EPI 3: Ch = f16(acc+bias)
#define ASTRIDE 80
#define STAGE_BYTES 15360
#define NSTAGE 3
template <int EPI>
__global__ __launch_bounds__(256, 2) void mma_gemm(const __half* __restrict__ A,
                                                   const __half* __restrict__ B,
                                                   const float* __restrict__ bias,
                                                   const float* __restrict__ resid,
                                                   float* __restrict__ Cf,
                                                   __half* __restrict__ Ch,
                                                   int Krow, int N) {
    __shared__ __align__(16) char sm[NSTAGE * STAGE_BYTES];
    uint32_t smBase = smem_u32(sm);
    int tid = threadIdx.x;
    int wid = tid >> 5, lane = tid & 31;
    int wm = wid >> 1, wn = wid & 1;
    int m0 = blockIdx.y << 7, n0 = blockIdx.x << 6;
    int niter = Krow >> 5;

    float acc[2][4][4];
#pragma unroll
    for (int t = 0; t < 2; t++)
#pragma unroll
        for (int j = 0; j < 4; j++)
#pragma unroll
            for (int e = 0; e < 4; e++) acc[t][j][e] = 0.f;

    int arow = tid >> 2, ach = tid & 3;
    const __half* gA0 = A + (size_t)m0 * Krow;
    const __half* gB0 = B + (size_t)(n0 + arow) * Krow + (ach << 3);

    uint32_t aOff = (uint32_t)((wm * 32 + (lane & 15)) * ASTRIDE + ((lane >> 4) << 4));
    uint32_t bOff = (uint32_t)((wn * 32 + (lane & 7) + ((lane >> 4) << 3)) * ASTRIDE +
                               (((lane >> 3) & 1) << 4));

#pragma unroll
    for (int st = 0; st < NSTAGE - 1; st++) {
        uint32_t sA = smBase + st * STAGE_BYTES;
        int k0 = st << 5;
#pragma unroll
        for (int i = 0; i < 2; i++) {
            int u = tid + (i << 8);
            int row = u >> 2, ch = u & 3;
            cp16(sA + row * ASTRIDE + ch * 16, gA0 + (size_t)row * Krow + k0 + (ch << 3));
        }
        cp16(sA + 10240 + arow * ASTRIDE + ach * 16, gB0 + k0);
        cp_commit();
    }

    int stC = 0, stP = NSTAGE - 1;
    for (int it = 0; it < niter; ++it) {
        cp_wait1();
        __syncthreads();
        if (it + NSTAGE - 1 < niter) {
            int k0 = (it + NSTAGE - 1) << 5;
            uint32_t sA = smBase + stP * STAGE_BYTES;
#pragma unroll
            for (int i = 0; i < 2; i++) {
                int u = tid + (i << 8);
                int row = u >> 2, ch = u & 3;
                cp16(sA + row * ASTRIDE + ch * 16, gA0 + (size_t)row * Krow + k0 + (ch << 3));
            }
            cp16(sA + 10240 + arow * ASTRIDE + ach * 16, gB0 + k0);
        }
        cp_commit();
        if (++stP == NSTAGE) stP = 0;

        uint32_t aBase = smBase + stC * STAGE_BYTES + aOff;
        uint32_t bBase = smBase + stC * STAGE_BYTES + 10240 + bOff;
        if (++stC == NSTAGE) stC = 0;
#pragma unroll
        for (int ks = 0; ks < 2; ks++) {
            uint32_t a[2][4], b[2][4];
            ldsm4(a[0], aBase + ks * 32);
            ldsm4(a[1], aBase + 16 * ASTRIDE + ks * 32);
            ldsm4(b[0], bBase + ks * 32);
            ldsm4(b[1], bBase + 16 * ASTRIDE + ks * 32);
#pragma unroll
            for (int t = 0; t < 2; t++) {
#pragma unroll
                for (int j = 0; j < 4; j++) {
                    uint32_t b0 = b[j >> 1][(j & 1) ? 2 : 0];
                    uint32_t b1 = b[j >> 1][(j & 1) ? 3 : 1];
                    mma16816(acc[t][j], a[t], b0, b1);
                }
            }
        }
    }

#pragma unroll
    for (int t = 0; t < 2; t++) {
        int row0 = m0 + wm * 32 + t * 16 + (lane >> 2);
        int row1 = row0 + 8;
#pragma unroll
        for (int j = 0; j < 4; j++) {
            int col = n0 + wn * 32 + j * 8 + ((lane & 3) << 1);
            float v0 = acc[t][j][0], v1 = acc[t][j][1];
            float v2 = acc[t][j][2], v3 = acc[t][j][3];
            if (EPI != 0 || bias) {
                float b0 = bias[col], b1 = bias[col + 1];
                v0 += b0; v1 += b1; v2 += b0; v3 += b1;
            }
            if (EPI == 1 || EPI == 3) {
                if (EPI == 1) {
                    v0 = 0.5f * v0 * (1.f + erff(v0 * 0.70710678118654752f));
                    v1 = 0.5f * v1 * (1.f + erff(v1 * 0.70710678118654752f));
                    v2 = 0.5f * v2 * (1.f + erff(v2 * 0.70710678118654752f));
                    v3 = 0.5f * v3 * (1.f + erff(v3 * 0.70710678118654752f));
                }
                *(__half2*)(Ch + (size_t)row0 * N + col) =
                    __halves2half2(__float2half_rn(v0), __float2half_rn(v1));
                *(__half2*)(Ch + (size_t)row1 * N + col) =
                    __halves2half2(__float2half_rn(v2), __float2half_rn(v3));
            } else {
                if (EPI == 2) {
                    float2 r0 = *(const float2*)(resid + (size_t)row0 * N + col);
                    float2 r1 = *(const float2*)(resid + (size_t)row1 * N + col);
                    v0 += r0.x; v1 += r0.y; v2 += r1.x; v3 += r1.y;
                }
                *(float2*)(Cf + (size_t)row0 * N + col) = make_float2(v0, v1);
                *(float2*)(Cf + (size_t)row1 * N + col) = make_float2(v2, v3);
            }
        }
    }
}

// =================== 64x64-tile variant (for N=256 GEMMs) ==========================
#define STAGE64 10240
template <int EPI>
__global__ __launch_bounds__(256, 3) void mma_gemm64(const __half* __restrict__ A,
                                                     const __half* __restrict__ B,
                                                     const float* __restrict__ bias,
                                                     const float* __restrict__ resid,
                                                     float* __restrict__ Cf,
                                                     int Krow, int N) {
    __shared__ __align__(16) char sm[NSTAGE * STAGE64];
    uint32_t smBase = smem_u32(sm);
    int tid = threadIdx.x;
    int wid = tid >> 5, lane = tid & 31;
    int wm = wid >> 1, wn = wid & 1;
    int m0 = blockIdx.y << 6, n0 = blockIdx.x << 6;
    int niter = Krow >> 5;

    float acc[4][4];
#pragma unroll
    for (int j = 0; j < 4; j++)
#pragma unroll
        for (int e = 0; e < 4; e++) acc[j][e] = 0.f;

    int arow = tid >> 2, ach = tid & 3;
    const __half* gA0 = A + (size_t)(m0 + arow) * Krow + (ach << 3);
    const __half* gB0 = B + (size_t)(n0 + arow) * Krow + (ach << 3);
    uint32_t sOff = arow * ASTRIDE + (ach << 4);

    uint32_t aOff = (uint32_t)((wm * 16 + (lane & 15)) * ASTRIDE + ((lane >> 4) << 4));
    uint32_t bOff = (uint32_t)(5120 + (wn * 32 + (lane & 7) + ((lane >> 4) << 3)) * ASTRIDE +
                               (((lane >> 3) & 1) << 4));

#pragma unroll
    for (int st = 0; st < NSTAGE - 1; st++) {
        uint32_t sA = smBase + st * STAGE64;
        int k0 = st << 5;
        cp16(sA + sOff, gA0 + k0);
        cp16(sA + 5120 + sOff, gB0 + k0);
        cp_commit();
    }

    int stC = 0, stP = NSTAGE - 1;
    for (int it = 0; it < niter; ++it) {
        cp_wait1();
        __syncthreads();
        if (it + NSTAGE - 1 < niter) {
            int k0 = (it + NSTAGE - 1) << 5;
            uint32_t sA = smBase + stP * STAGE64;
            cp16(sA + sOff, gA0 + k0);
            cp16(sA + 5120 + sOff, gB0 + k0);
        }
        cp_commit();
        if (++stP == NSTAGE) stP = 0;

        uint32_t aBase = smBase + stC * STAGE64 + aOff;
        uint32_t bBase = smBase + stC * STAGE64 + bOff;
        if (++stC == NSTAGE) stC = 0;
#pragma unroll
        for (int ks = 0; ks < 2; ks++) {
            uint32_t a[4], b[2][4];
            ldsm4(a, aBase + ks * 32);
            ldsm4(b[0], bBase + ks * 32);
            ldsm4(b[1], bBase + 16 * ASTRIDE + ks * 32);
#pragma unroll
            for (int j = 0; j < 4; j++) {
                uint32_t b0 = b[j >> 1][(j & 1) ? 2 : 0];
                uint32_t b1 = b[j >> 1][(j & 1) ? 3 : 1];
                mma16816(acc[j], a, b0, b1);
            }
        }
    }

    int row0 = m0 + wm * 16 + (lane >> 2);
    int row1 = row0 + 8;
#pragma unroll
    for (int j = 0; j < 4; j++) {
        int col = n0 + wn * 32 + j * 8 + ((lane & 3) << 1);
        float v0 = acc[j][0], v1 = acc[j][1], v2 = acc[j][2], v3 = acc[j][3];
        if (bias) {
            float b0 = bias[col], b1 = bias[col + 1];
            v0 += b0; v1 += b1; v2 += b0; v3 += b1;
        }
        if (EPI == 2) {
            float2 r0 = *(const float2*)(resid + (size_t)row0 * N + col);
            float2 r1 = *(const float2*)(resid + (size_t)row1 * N + col);
            v0 += r0.x; v1 += r0.y; v2 += r1.x; v3 += r1.y;
        }
        *(float2*)(Cf + (size_t)row0 * N + col) = make_float2(v0, v1);
        *(float2*)(Cf + (size_t)row1 * N + col) = make_float2(v2, v3);
    }
}

// =================== host launch ===================
extern "C" void kernel_launch(void* const* d_in, const int* in_sizes, int n_in,
                              void* d_out, int out_size) {
    (void)in_sizes; (void)n_in; (void)out_size;
    const float* grd2sat = (const float*)d_in[0];
    const float* grd_x   = (const float*)d_in[1];
    const float* u       = (const float*)d_in[2];
    const float* ln_q_w  = (const float*)d_in[3];
    const float* ln_q_b  = (const float*)d_in[4];
    const float* ln_k_w  = (const float*)d_in[5];
    const float* ln_k_b  = (const float*)d_in[6];
    const float* ln_v_w  = (const float*)d_in[7];
    const float* ln_v_b  = (const float*)d_in[8];
    const float* Wq      = (const float*)d_in[9];
    const float* Wk      = (const float*)d_in[10];
    const float* Wv      = (const float*)d_in[11];
    const float* Wproj   = (const float*)d_in[12];
    const float* bproj   = (const float*)d_in[13];
    const float* ln_pre_w  = (const float*)d_in[14];
    const float* ln_pre_b  = (const float*)d_in[15];
    const float* Wm1     = (const float*)d_in[16];
    const float* bm1     = (const float*)d_in[17];
    const float* Wm2     = (const float*)d_in[18];
    const float* bm2     = (const float*)d_in[19];
    const float* ln_post_w = (const float*)d_in[20];
    const float* ln_post_b = (const float*)d_in[21];
    float* out = (float*)d_out;

    __half *Xn, *Wkv, *KVh, *t16, *a16, *z216, *h16, *Wq2, *Wp2, *Wm1c, *Wm2c;
    float *bcat, *x, *q, *z1, *z2, *z3;
    cudaGetSymbolAddress((void**)&Xn, g_Xn);
    cudaGetSymbolAddress((void**)&Wkv, g_Wkv);
    cudaGetSymbolAddress((void**)&bcat, g_bcat);
    cudaGetSymbolAddress((void**)&KVh, g_KVh);
    cudaGetSymbolAddress((void**)&x, g_x);
    cudaGetSymbolAddress((void**)&t16, g_t16);
    cudaGetSymbolAddress((void**)&q, g_q);
    cudaGetSymbolAddress((void**)&a16, g_a16);
    cudaGetSymbolAddress((void**)&z1, g_z1);
    cudaGetSymbolAddress((void**)&z2, g_z2);
    cudaGetSymbolAddress((void**)&z216, g_z216);
    cudaGetSymbolAddress((void**)&h16, g_h16);
    cudaGetSymbolAddress((void**)&z3, g_z3);
    cudaGetSymbolAddress((void**)&Wq2, g_Wq2);
    cudaGetSymbolAddress((void**)&Wp2, g_Wp2);
    cudaGetSymbolAddress((void**)&Wm1c, g_Wm1c);
    cudaGetSymbolAddress((void**)&Wm2c, g_Wm2c);

    WtJobs jobs;
    for (int i = 0; i < 2; i++) {
        jobs.j[i * 4 + 0] = {Wq + i * 65536, Wq2 + i * 256 * 256, 256, 256};
        jobs.j[i * 4 + 1] = {Wproj + i * 65536, Wp2 + i * 256 * 256, 256, 256};
        jobs.j[i * 4 + 2] = {Wm1 + i * 131072, Wm1c + i * 512 * 256, 256, 512};
        jobs.j[i * 4 + 3] = {Wm2 + i * 131072, Wm2c + i * 256 * 512, 512, 256};
    }

    // ---- prep (one fused kernel) ----
    prep_kernel<<<1280, 256>>>(grd_x, Wk, Wv, ln_k_w, ln_v_w, ln_k_b, ln_v_b,
                               Xn, Wkv, bcat, jobs);

    // KVh = f16(Xn @ Wkv + bcat) : (4096 x 1024)
    mma_gemm<3><<<dim3(16, 32), 256>>>(Xn, Wkv, bcat, nullptr, nullptr, KVh, 256, 1024);
    transpose_scale<<<dim3(128, 8), dim3(32, 8)>>>(grd2sat, x, 256, 4096);

    for (int i = 0; i < 2; i++) {
        if (i == 0)
            ln_kernel<<<512, 256>>>(x, ln_q_w, ln_q_b, nullptr, t16);
        mma_gemm64<0><<<dim3(4, 64), 256>>>(t16, Wq2 + i * 256 * 256, nullptr, nullptr, q,
                                            256, 256);
        attn_kernel<<<4096, 256>>>(q, KVh, u, i * 512, a16);
        mma_gemm64<0><<<dim3(4, 64), 256>>>(a16, Wp2 + i * 256 * 256, bproj + i * 256,
                                            nullptr, z1, 256, 256);
        ln_kernel<<<512, 256>>>(z1, ln_pre_w + i * 256, ln_pre_b + i * 256, z2, z216);
        mma_gemm<1><<<dim3(8, 32), 256>>>(z216, Wm1c + i * 512 * 256, bm1 + i * 512,
                                          nullptr, nullptr, h16, 256, 512);
        mma_gemm64<2><<<dim3(4, 64), 256>>>(h16, Wm2c + i * 256 * 512, bm2 + i * 256, z2,
                                            z3, 512, 256);
        if (i == 0)
            ln2_kernel<<<512, 256>>>(z3, ln_post_w, ln_post_b, ln_q_w + 256, ln_q_b + 256,
                                     t16);
    }

    final_kernel<<<128, 256>>>(z3, ln_post_w + 256, ln_post_b + 256, out);
}

// round 15
// speedup vs baseline: 1.2600x; 1.0058x over previous
#include <cuda_runtime.h>
#include <cuda_fp16.h>
#include <math.h>
#include <stdint.h>

#define ATTN_SCALE 0.17677669529663687f  // 32^-0.5

__device__ __forceinline__ uint32_t smem_u32(const void* p) {
    uint32_t a;
    asm("{ .reg .u64 t; cvta.to.shared.u64 t, %1; cvt.u32.u64 %0, t; }" : "=r"(a) : "l"(p));
    return a;
}
__device__ __forceinline__ void cp16(uint32_t s, const void* g) {
    asm volatile("cp.async.cg.shared.global [%0], [%1], 16;" :: "r"(s), "l"(g));
}
__device__ __forceinline__ void cp_commit() { asm volatile("cp.async.commit_group;"); }
__device__ __forceinline__ void cp_wait1() { asm volatile("cp.async.wait_group 1;"); }
__device__ __forceinline__ void ldsm4(uint32_t r[4], uint32_t addr) {
    asm volatile("ldmatrix.sync.aligned.m8n8.x4.shared.b16 {%0,%1,%2,%3}, [%4];"
                 : "=r"(r[0]), "=r"(r[1]), "=r"(r[2]), "=r"(r[3]) : "r"(addr));
}
__device__ __forceinline__ void mma16816(float c[4], const uint32_t a[4], uint32_t b0,
                                         uint32_t b1) {
    asm volatile(
        "mma.sync.aligned.m16n8k16.row.col.f32.f16.f16.f32 "
        "{%0,%1,%2,%3}, {%4,%5,%6,%7}, {%8,%9}, {%0,%1,%2,%3};"
        : "+f"(c[0]), "+f"(c[1]), "+f"(c[2]), "+f"(c[3])
        : "r"(a[0]), "r"(a[1]), "r"(a[2]), "r"(a[3]), "r"(b0), "r"(b1));
}

// =================== device scratch ===================
__device__ __half g_Xn[4096 * 256];
__device__ __half g_Wkv[1024 * 256];
__device__ float g_bcat[1024];
__device__ __half g_KVh[4096 * 1024];
__device__ float g_x[4096 * 256];
__device__ __half g_t16[4096 * 256];
__device__ __half g_q16[4096 * 256];
__device__ __half g_a16[4096 * 256];
__device__ float g_z1[4096 * 256];
__device__ float g_z2[4096 * 256];
__device__ __half g_z216[4096 * 256];
__device__ __half g_h16[4096 * 512];
__device__ float g_z3[4096 * 256];
__device__ __half g_Wq2[2 * 256 * 256];
__device__ __half g_Wp2[2 * 256 * 256];
__device__ __half g_Wm1c[2 * 512 * 256];
__device__ __half g_Wm2c[2 * 256 * 512];

// =================== fused prep kernel ===================
struct WtJob { const float* src; __half* dst; int K; int N; float scale; };
struct WtJobs { WtJob j[8]; };
__global__ __launch_bounds__(256) void prep_kernel(
    const float* __restrict__ grd_x,
    const float* __restrict__ Wk, const float* __restrict__ Wv,
    const float* __restrict__ lnkw, const float* __restrict__ lnvw,
    const float* __restrict__ lnkb, const float* __restrict__ lnvb,
    __half* __restrict__ Xn, __half* __restrict__ Wkv, float* __restrict__ bcat,
    WtJobs jobs) {
    __shared__ float tile[256][33];
    __shared__ float ps[8][32], pq[8][32];
    __shared__ float cmu[32], crs[32];
    int bid = blockIdx.x;
    int tid = threadIdx.x;
    int tx = tid & 31, ty = tid >> 5;

    if (bid < 128) {
        int j0 = bid * 32;
        float s = 0.f, q = 0.f;
#pragma unroll
        for (int t = 0; t < 32; t++) {
            int c = t * 8 + ty;
            float v = grd_x[(size_t)c * 4096 + j0 + tx];
            tile[c][tx] = v;
            s += v; q += v * v;
        }
        ps[ty][tx] = s; pq[ty][tx] = q;
        __syncthreads();
        if (ty == 0) {
            float ss = 0.f, qq = 0.f;
#pragma unroll
            for (int r = 0; r < 8; r++) { ss += ps[r][tx]; qq += pq[r][tx]; }
            float mu = ss * (1.f / 256.f);
            cmu[tx] = mu;
            crs[tx] = rsqrtf(qq * (1.f / 256.f) - mu * mu + 1e-5f);
        }
        __syncthreads();
#pragma unroll
        for (int r = 0; r < 4; r++) {
            int jj = ty * 4 + r;
            float mu = cmu[jj], rs = crs[jj];
            size_t rb = (size_t)(j0 + jj) * 256 + tx * 8;
            __half h[8];
#pragma unroll
            for (int e = 0; e < 8; e++)
                h[e] = __float2half_rn((tile[tx * 8 + e][jj] - mu) * rs);
            *(uint4*)(Xn + rb) = *(uint4*)h;
        }
    } else if (bid < 384) {
        int local = bid - 128;
        int ct = local & 7, ot = (local >> 3) & 7, seg = local >> 6;
        int i = seg >> 1, isv = seg & 1;
        const float* W = (isv ? Wv : Wk) + i * 65536;
        const float* lw = (isv ? lnvw : lnkw) + i * 256;
        int c0 = ct * 32, o0 = ot * 32;
        float (*t)[33] = (float (*)[33])tile;
#pragma unroll
        for (int s = 0; s < 4; s++) {
            int c = c0 + ty + s * 8;
            t[ty + s * 8][tx] = W[(size_t)c * 256 + o0 + tx] * lw[c];
        }
        __syncthreads();
#pragma unroll
        for (int s = 0; s < 4; s++) {
            int o = o0 + ty + s * 8;
            size_t rb = (size_t)(seg * 256 + o) * 256;
            Wkv[rb + c0 + tx] = __float2half_rn(t[tx][ty + s * 8]);
        }
    } else if (bid < 512) {
        int o = (bid - 384) * 8 + ty;
        int seg = o >> 8, oo = o & 255;
        int i = seg >> 1, isv = seg & 1;
        const float* W = (isv ? Wv : Wk) + i * 65536;
        const float* b = (isv ? lnvb : lnkb) + i * 256;
        float s = 0.f;
#pragma unroll
        for (int t = 0; t < 8; t++) {
            int c = tx + t * 32;
            s += b[c] * W[(size_t)c * 256 + oo];
        }
#pragma unroll
        for (int off = 16; off; off >>= 1) s += __shfl_xor_sync(0xffffffffu, s, off);
        if (tx == 0) bcat[o] = s;
    } else {
        int local = bid - 512;
        const int prefix[9] = {0, 64, 128, 256, 384, 448, 512, 640, 768};
        int jb = 0;
#pragma unroll
        for (int t = 1; t < 8; t++) if (local >= prefix[t]) jb = t;
        WtJob job = jobs.j[jb];
        int loc = local - prefix[jb];
        int ktiles = job.K >> 5;
        int kt = loc % ktiles, nt = loc / ktiles;
        int k0 = kt * 32, n0 = nt * 32;
        float (*t)[33] = (float (*)[33])tile;
#pragma unroll
        for (int s = 0; s < 4; s++) {
            int k = k0 + ty + s * 8;
            t[ty + s * 8][tx] = job.src[(size_t)k * job.N + n0 + tx] * job.scale;
        }
        __syncthreads();
#pragma unroll
        for (int s = 0; s < 4; s++) {
            int n = n0 + ty + s * 8;
            job.dst[(size_t)n * job.K + k0 + tx] = __float2half_rn(t[tx][ty + s * 8]);
        }
    }
}

// LayerNorm, warp per row; optional fp32 out and/or fp16 out
__global__ __launch_bounds__(256) void ln_kernel(const float* __restrict__ in,
                                                 const float* __restrict__ w,
                                                 const float* __restrict__ b,
                                                 float* __restrict__ outF,
                                                 __half* __restrict__ outH) {
    int wid = threadIdx.x >> 5, lane = threadIdx.x & 31;
    int m = blockIdx.x * 8 + wid;
    const float4* ip = (const float4*)(in + (size_t)m * 256 + lane * 8);
    float4 v0 = ip[0], v1 = ip[1];
    float s = v0.x + v0.y + v0.z + v0.w + v1.x + v1.y + v1.z + v1.w;
#pragma unroll
    for (int o = 16; o; o >>= 1) s += __shfl_xor_sync(0xffffffffu, s, o);
    float mean = s * (1.f / 256.f);
    float x[8] = {v0.x - mean, v0.y - mean, v0.z - mean, v0.w - mean,
                  v1.x - mean, v1.y - mean, v1.z - mean, v1.w - mean};
    float q = 0.f;
#pragma unroll
    for (int e = 0; e < 8; e++) q = fmaf(x[e], x[e], q);
#pragma unroll
    for (int o = 16; o; o >>= 1) q += __shfl_xor_sync(0xffffffffu, q, o);
    float rstd = rsqrtf(q * (1.f / 256.f) + 1e-5f);
    float4 w0 = *(const float4*)(w + lane * 8), w1 = *(const float4*)(w + lane * 8 + 4);
    float4 b0 = *(const float4*)(b + lane * 8), b1 = *(const float4*)(b + lane * 8 + 4);
    float y[8];
    y[0] = x[0] * rstd * w0.x + b0.x; y[1] = x[1] * rstd * w0.y + b0.y;
    y[2] = x[2] * rstd * w0.z + b0.z; y[3] = x[3] * rstd * w0.w + b0.w;
    y[4] = x[4] * rstd * w1.x + b1.x; y[5] = x[5] * rstd * w1.y + b1.y;
    y[6] = x[6] * rstd * w1.z + b1.z; y[7] = x[7] * rstd * w1.w + b1.w;
    if (outF) {
        float4* op = (float4*)(outF + (size_t)m * 256 + lane * 8);
        op[0] = make_float4(y[0], y[1], y[2], y[3]);
        op[1] = make_float4(y[4], y[5], y[6], y[7]);
    }
    if (outH) {
        __half h[8];
#pragma unroll
        for (int e = 0; e < 8; e++) h[e] = __float2half_rn(y[e]);
        *(uint4*)(outH + (size_t)m * 256 + lane * 8) = *(uint4*)h;
    }
}

// fused LN_post + LN_q at block boundary: z3 -> t16 (fp16)
__global__ __launch_bounds__(256) void ln2_kernel(const float* __restrict__ in,
                                                  const float* __restrict__ w1,
                                                  const float* __restrict__ b1,
                                                  const float* __restrict__ w2,
                                                  const float* __restrict__ b2,
                                                  __half* __restrict__ outH) {
    int wid = threadIdx.x >> 5, lane = threadIdx.x & 31;
    int m = blockIdx.x * 8 + wid;
    const float4* ip = (const float4*)(in + (size_t)m * 256 + lane * 8);
    float4 v0 = ip[0], v1 = ip[1];
    float x[8] = {v0.x, v0.y, v0.z, v0.w, v1.x, v1.y, v1.z, v1.w};
    float s = 0.f;
#pragma unroll
    for (int e = 0; e < 8; e++) s += x[e];
#pragma unroll
    for (int o = 16; o; o >>= 1) s += __shfl_xor_sync(0xffffffffu, s, o);
    float mean = s * (1.f / 256.f);
    float q = 0.f;
#pragma unroll
    for (int e = 0; e < 8; e++) { x[e] -= mean; q = fmaf(x[e], x[e], q); }
#pragma unroll
    for (int o = 16; o; o >>= 1) q += __shfl_xor_sync(0xffffffffu, q, o);
    float rstd = rsqrtf(q * (1.f / 256.f) + 1e-5f);
    float4 wA0 = *(const float4*)(w1 + lane * 8), wA1 = *(const float4*)(w1 + lane * 8 + 4);
    float4 bA0 = *(const float4*)(b1 + lane * 8), bA1 = *(const float4*)(b1 + lane * 8 + 4);
    float wa[8] = {wA0.x, wA0.y, wA0.z, wA0.w, wA1.x, wA1.y, wA1.z, wA1.w};
    float ba[8] = {bA0.x, bA0.y, bA0.z, bA0.w, bA1.x, bA1.y, bA1.z, bA1.w};
    float y[8];
#pragma unroll
    for (int e = 0; e < 8; e++) y[e] = x[e] * rstd * wa[e] + ba[e];
    float s2 = 0.f;
#pragma unroll
    for (int e = 0; e < 8; e++) s2 += y[e];
#pragma unroll
    for (int o = 16; o; o >>= 1) s2 += __shfl_xor_sync(0xffffffffu, s2, o);
    float mean2 = s2 * (1.f / 256.f);
    float q2 = 0.f;
#pragma unroll
    for (int e = 0; e < 8; e++) { y[e] -= mean2; q2 = fmaf(y[e], y[e], q2); }
#pragma unroll
    for (int o = 16; o; o >>= 1) q2 += __shfl_xor_sync(0xffffffffu, q2, o);
    float rstd2 = rsqrtf(q2 * (1.f / 256.f) + 1e-5f);
    float4 wB0 = *(const float4*)(w2 + lane * 8), wB1 = *(const float4*)(w2 + lane * 8 + 4);
    float4 bB0 = *(const float4*)(b2 + lane * 8), bB1 = *(const float4*)(b2 + lane * 8 + 4);
    float wb[8] = {wB0.x, wB0.y, wB0.z, wB0.w, wB1.x, wB1.y, wB1.z, wB1.w};
    float bb[8] = {bB0.x, bB0.y, bB0.z, bB0.w, bB1.x, bB1.y, bB1.z, bB1.w};
    __half h[8];
#pragma unroll
    for (int e = 0; e < 8; e++)
        h[e] = __float2half_rn(y[e] * rstd2 * wb[e] + bb[e]);
    *(uint4*)(outH + (size_t)m * 256 + lane * 8) = *(uint4*)h;
}

// fused final: z3 -> LN_post -> L2-normalize -> transposed out (256 x 4096)
__global__ __launch_bounds__(256) void final_kernel(const float* __restrict__ in,
                                                    const float* __restrict__ w,
                                                    const float* __restrict__ b,
                                                    float* __restrict__ out) {
    __shared__ float t[32][257];
    int tid = threadIdx.x;
    int wid = tid >> 5, lane = tid & 31;
    int m0 = blockIdx.x * 32;
#pragma unroll
    for (int r = 0; r < 4; r++) {
        int lr = wid * 4 + r;
        int m = m0 + lr;
        const float4* ip = (const float4*)(in + (size_t)m * 256 + lane * 8);
        float4 v0 = ip[0], v1 = ip[1];
        float x[8] = {v0.x, v0.y, v0.z, v0.w, v1.x, v1.y, v1.z, v1.w};
        float s = 0.f;
#pragma unroll
        for (int e = 0; e < 8; e++) s += x[e];
#pragma unroll
        for (int o = 16; o; o >>= 1) s += __shfl_xor_sync(0xffffffffu, s, o);
        float mean = s * (1.f / 256.f);
        float q = 0.f;
#pragma unroll
        for (int e = 0; e < 8; e++) { x[e] -= mean; q = fmaf(x[e], x[e], q); }
#pragma unroll
        for (int o = 16; o; o >>= 1) q += __shfl_xor_sync(0xffffffffu, q, o);
        float rstd = rsqrtf(q * (1.f / 256.f) + 1e-5f);
        float4 w0 = *(const float4*)(w + lane * 8), w1 = *(const float4*)(w + lane * 8 + 4);
        float4 b0 = *(const float4*)(b + lane * 8), b1 = *(const float4*)(b + lane * 8 + 4);
        float wa[8] = {w0.x, w0.y, w0.z, w0.w, w1.x, w1.y, w1.z, w1.w};
        float ba[8] = {b0.x, b0.y, b0.z, b0.w, b1.x, b1.y, b1.z, b1.w};
        float y[8];
        float q2 = 0.f;
#pragma unroll
        for (int e = 0; e < 8; e++) {
            y[e] = x[e] * rstd * wa[e] + ba[e];
            q2 = fmaf(y[e], y[e], q2);
        }
#pragma unroll
        for (int o = 16; o; o >>= 1) q2 += __shfl_xor_sync(0xffffffffu, q2, o);
        float inv = 1.f / fmaxf(sqrtf(q2), 1e-12f);
#pragma unroll
        for (int e = 0; e < 8; e++) t[lr][lane * 8 + e] = y[e] * inv;
    }
    __syncthreads();
    int tx = tid & 31, ty = tid >> 5;
#pragma unroll
    for (int c0 = 0; c0 < 256; c0 += 8) {
        int c = c0 + ty;
        out[(size_t)c * 4096 + m0 + tx] = t[tx][c];
    }
}

__global__ void transpose_scale(const float* __restrict__ in, float* __restrict__ out,
                                int R, int Cd) {
    __shared__ float t[32][33];
    int bx = blockIdx.x * 32, by = blockIdx.y * 32;
    int x = threadIdx.x, y0 = threadIdx.y;
    for (int yy = y0; yy < 32; yy += 8)
        t[yy][x] = in[(size_t)(by + yy) * Cd + bx + x];
    __syncthreads();
    for (int yy = y0; yy < 32; yy += 8)
        out[(size_t)(bx + yy) * R + by + x] = t[x][yy];
}

// =================== attention: R10 layout, fp16 KV + fp16 q (scale folded) ========
__global__ __launch_bounds__(256) void attn_kernel(const __half* __restrict__ q16,
                                                   const __half* __restrict__ KVh,
                                                   const float* __restrict__ u,
                                                   int kvOff,
                                                   __half* __restrict__ a16) {
    int m = blockIdx.x;
    int h = threadIdx.x >> 5;
    int lane = threadIdx.x & 31;
    int g = lane >> 3, e = lane & 7;
    float uf = floorf(u[m]);
    int jL = (int)fminf(fmaxf(uf, 0.f), 127.f);
    int jR = (int)fminf(fmaxf(uf + 1.f, 0.f), 127.f);
    int base = kvOff + h * 32 + e * 4;
    uint2 qraw = *(const uint2*)(q16 + (size_t)m * 256 + h * 32 + e * 4);
    float2 q01 = __half22float2(*(const __half2*)&qraw.x);
    float2 q23 = __half22float2(*(const __half2*)&qraw.y);
    float4 qv = make_float4(q01.x, q01.y, q23.x, q23.y);

    float s[16];
#pragma unroll
    for (int t = 0; t < 16; t++) {
        int n = t * 4 + g;
        int j = ((n & 31) << 7) + ((n < 32) ? jL : jR);
        uint2 raw = *(const uint2*)(KVh + (size_t)j * 1024 + base);
        float2 f01 = __half22float2(*(const __half2*)&raw.x);
        float2 f23 = __half22float2(*(const __half2*)&raw.y);
        float p = qv.x * f01.x + qv.y * f01.y + qv.z * f23.x + qv.w * f23.y;
        p += __shfl_xor_sync(0xffffffffu, p, 1);
        p += __shfl_xor_sync(0xffffffffu, p, 2);
        p += __shfl_xor_sync(0xffffffffu, p, 4);
        s[t] = p;
    }
    float mx = s[0];
#pragma unroll
    for (int t = 1; t < 16; t++) mx = fmaxf(mx, s[t]);
#pragma unroll
    for (int o = 16; o; o >>= 1) mx = fmaxf(mx, __shfl_xor_sync(0xffffffffu, mx, o));
    float sum = 0.f;
#pragma unroll
    for (int t = 0; t < 16; t++) { s[t] = expf(s[t] - mx); sum += s[t]; }
#pragma unroll
    for (int o = 16; o; o >>= 1) sum += __shfl_xor_sync(0xffffffffu, sum, o);
    float inv = 8.f / sum;

    float4 acc = make_float4(0.f, 0.f, 0.f, 0.f);
#pragma unroll
    for (int t = 0; t < 16; t++) {
        int n = t * 4 + g;
        int j = ((n & 31) << 7) + ((n < 32) ? jL : jR);
        uint2 raw = *(const uint2*)(KVh + (size_t)j * 1024 + base + 256);
        float2 f01 = __half22float2(*(const __half2*)&raw.x);
        float2 f23 = __half22float2(*(const __half2*)&raw.y);
        float p = s[t] * inv;
        acc.x = fmaf(p, f01.x, acc.x);
        acc.y = fmaf(p, f01.y, acc.y);
        acc.z = fmaf(p, f23.x, acc.z);
        acc.w = fmaf(p, f23.y, acc.w);
    }
#pragma unroll
    for (int o = 8; o <= 16; o <<= 1) {
        acc.x += __shfl_xor_sync(0xffffffffu, acc.x, o);
        acc.y += __shfl_xor_sync(0xffffffffu, acc.y, o);
        acc.z += __shfl_xor_sync(0xffffffffu, acc.z, o);
        acc.w += __shfl_xor_sync(0xffffffffu, acc.w, o);
    }
    if (g == 0) {
        __half h4[4] = {__float2half_rn(acc.x), __float2half_rn(acc.y),
                        __float2half_rn(acc.z), __float2half_rn(acc.w)};
        *(uint2*)(a16 + (size_t)m * 256 + h * 32 + e * 4) = *(uint2*)h4;
    }
}

// =================== mma.sync fp16 GEMM: 128x64 tile, 3-stage =====================
// EPI 0: Cf = acc (+bias)  EPI 1: Ch = f16(gelu(acc+bias))  EPI 2: Cf = acc+bias+resid
// EPI 3: Ch = f16(acc+bias)
#define ASTRIDE 80
#define STAGE_BYTES 15360
#define NSTAGE 3
template <int EPI>
__global__ __launch_bounds__(256, 2) void mma_gemm(const __half* __restrict__ A,
                                                   const __half* __restrict__ B,
                                                   const float* __restrict__ bias,
                                                   const float* __restrict__ resid,
                                                   float* __restrict__ Cf,
                                                   __half* __restrict__ Ch,
                                                   int Krow, int N) {
    __shared__ __align__(16) char sm[NSTAGE * STAGE_BYTES];
    uint32_t smBase = smem_u32(sm);
    int tid = threadIdx.x;
    int wid = tid >> 5, lane = tid & 31;
    int wm = wid >> 1, wn = wid & 1;
    int m0 = blockIdx.y << 7, n0 = blockIdx.x << 6;
    int niter = Krow >> 5;

    float acc[2][4][4];
#pragma unroll
    for (int t = 0; t < 2; t++)
#pragma unroll
        for (int j = 0; j < 4; j++)
#pragma unroll
            for (int e = 0; e < 4; e++) acc[t][j][e] = 0.f;

    int arow = tid >> 2, ach = tid & 3;
    const __half* gA0 = A + (size_t)m0 * Krow;
    const __half* gB0 = B + (size_t)(n0 + arow) * Krow + (ach << 3);

    uint32_t aOff = (uint32_t)((wm * 32 + (lane & 15)) * ASTRIDE + ((lane >> 4) << 4));
    uint32_t bOff = (uint32_t)((wn * 32 + (lane & 7) + ((lane >> 4) << 3)) * ASTRIDE +
                               (((lane >> 3) & 1) << 4));

#pragma unroll
    for (int st = 0; st < NSTAGE - 1; st++) {
        uint32_t sA = smBase + st * STAGE_BYTES;
        int k0 = st << 5;
#pragma unroll
        for (int i = 0; i < 2; i++) {
            int u = tid + (i << 8);
            int row = u >> 2, ch = u & 3;
            cp16(sA + row * ASTRIDE + ch * 16, gA0 + (size_t)row * Krow + k0 + (ch << 3));
        }
        cp16(sA + 10240 + arow * ASTRIDE + ach * 16, gB0 + k0);
        cp_commit();
    }

    int stC = 0, stP = NSTAGE - 1;
    for (int it = 0; it < niter; ++it) {
        cp_wait1();
        __syncthreads();
        if (it + NSTAGE - 1 < niter) {
            int k0 = (it + NSTAGE - 1) << 5;
            uint32_t sA = smBase + stP * STAGE_BYTES;
#pragma unroll
            for (int i = 0; i < 2; i++) {
                int u = tid + (i << 8);
                int row = u >> 2, ch = u & 3;
                cp16(sA + row * ASTRIDE + ch * 16, gA0 + (size_t)row * Krow + k0 + (ch << 3));
            }
            cp16(sA + 10240 + arow * ASTRIDE + ach * 16, gB0 + k0);
        }
        cp_commit();
        if (++stP == NSTAGE) stP = 0;

        uint32_t aBase = smBase + stC * STAGE_BYTES + aOff;
        uint32_t bBase = smBase + stC * STAGE_BYTES + 10240 + bOff;
        if (++stC == NSTAGE) stC = 0;
#pragma unroll
        for (int ks = 0; ks < 2; ks++) {
            uint32_t a[2][4], b[2][4];
            ldsm4(a[0], aBase + ks * 32);
            ldsm4(a[1], aBase + 16 * ASTRIDE + ks * 32);
            ldsm4(b[0], bBase + ks * 32);
            ldsm4(b[1], bBase + 16 * ASTRIDE + ks * 32);
#pragma unroll
            for (int t = 0; t < 2; t++) {
#pragma unroll
                for (int j = 0; j < 4; j++) {
                    uint32_t b0 = b[j >> 1][(j & 1) ? 2 : 0];
                    uint32_t b1 = b[j >> 1][(j & 1) ? 3 : 1];
                    mma16816(acc[t][j], a[t], b0, b1);
                }
            }
        }
    }

#pragma unroll
    for (int t = 0; t < 2; t++) {
        int row0 = m0 + wm * 32 + t * 16 + (lane >> 2);
        int row1 = row0 + 8;
#pragma unroll
        for (int j = 0; j < 4; j++) {
            int col = n0 + wn * 32 + j * 8 + ((lane & 3) << 1);
            float v0 = acc[t][j][0], v1 = acc[t][j][1];
            float v2 = acc[t][j][2], v3 = acc[t][j][3];
            if (EPI != 0 || bias) {
                float b0 = bias[col], b1 = bias[col + 1];
                v0 += b0; v1 += b1; v2 += b0; v3 += b1;
            }
            if (EPI == 1 || EPI == 3) {
                if (EPI == 1) {
                    v0 = 0.5f * v0 * (1.f + erff(v0 * 0.70710678118654752f));
                    v1 = 0.5f * v1 * (1.f + erff(v1 * 0.70710678118654752f));
                    v2 = 0.5f * v2 * (1.f + erff(v2 * 0.70710678118654752f));
                    v3 = 0.5f * v3 * (1.f + erff(v3 * 0.70710678118654752f));
                }
                *(__half2*)(Ch + (size_t)row0 * N + col) =
                    __halves2half2(__float2half_rn(v0), __float2half_rn(v1));
                *(__half2*)(Ch + (size_t)row1 * N + col) =
                    __halves2half2(__float2half_rn(v2), __float2half_rn(v3));
            } else {
                if (EPI == 2) {
                    float2 r0 = *(const float2*)(resid + (size_t)row0 * N + col);
                    float2 r1 = *(const float2*)(resid + (size_t)row1 * N + col);
                    v0 += r0.x; v1 += r0.y; v2 += r1.x; v3 += r1.y;
                }
                *(float2*)(Cf + (size_t)row0 * N + col) = make_float2(v0, v1);
                *(float2*)(Cf + (size_t)row1 * N + col) = make_float2(v2, v3);
            }
        }
    }
}

// =================== 64x64-tile variant (for N=256 GEMMs) ==========================
// EPI 0: Cf = acc (+bias)   EPI 2: Cf = acc+bias+resid   EPI 3: Ch = f16(acc (+bias))
#define STAGE64 10240
template <int EPI>
__global__ __launch_bounds__(256, 3) void mma_gemm64(const __half* __restrict__ A,
                                                     const __half* __restrict__ B,
                                                     const float* __restrict__ bias,
                                                     const float* __restrict__ resid,
                                                     float* __restrict__ Cf,
                                                     __half* __restrict__ Ch,
                                                     int Krow, int N) {
    __shared__ __align__(16) char sm[NSTAGE * STAGE64];
    uint32_t smBase = smem_u32(sm);
    int tid = threadIdx.x;
    int wid = tid >> 5, lane = tid & 31;
    int wm = wid >> 1, wn = wid & 1;
    int m0 = blockIdx.y << 6, n0 = blockIdx.x << 6;
    int niter = Krow >> 5;

    float acc[4][4];
#pragma unroll
    for (int j = 0; j < 4; j++)
#pragma unroll
        for (int e = 0; e < 4; e++) acc[j][e] = 0.f;

    int arow = tid >> 2, ach = tid & 3;
    const __half* gA0 = A + (size_t)(m0 + arow) * Krow + (ach << 3);
    const __half* gB0 = B + (size_t)(n0 + arow) * Krow + (ach << 3);
    uint32_t sOff = arow * ASTRIDE + (ach << 4);

    uint32_t aOff = (uint32_t)((wm * 16 + (lane & 15)) * ASTRIDE + ((lane >> 4) << 4));
    uint32_t bOff = (uint32_t)(5120 + (wn * 32 + (lane & 7) + ((lane >> 4) << 3)) * ASTRIDE +
                               (((lane >> 3) & 1) << 4));

#pragma unroll
    for (int st = 0; st < NSTAGE - 1; st++) {
        uint32_t sA = smBase + st * STAGE64;
        int k0 = st << 5;
        cp16(sA + sOff, gA0 + k0);
        cp16(sA + 5120 + sOff, gB0 + k0);
        cp_commit();
    }

    int stC = 0, stP = NSTAGE - 1;
    for (int it = 0; it < niter; ++it) {
        cp_wait1();
        __syncthreads();
        if (it + NSTAGE - 1 < niter) {
            int k0 = (it + NSTAGE - 1) << 5;
            uint32_t sA = smBase + stP * STAGE64;
            cp16(sA + sOff, gA0 + k0);
            cp16(sA + 5120 + sOff, gB0 + k0);
        }
        cp_commit();
        if (++stP == NSTAGE) stP = 0;

        uint32_t aBase = smBase + stC * STAGE64 + aOff;
        uint32_t bBase = smBase + stC * STAGE64 + bOff;
        if (++stC == NSTAGE) stC = 0;
#pragma unroll
        for (int ks = 0; ks < 2; ks++) {
            uint32_t a[4], b[2][4];
            ldsm4(a, aBase + ks * 32);
            ldsm4(b[0], bBase + ks * 32);
            ldsm4(b[1], bBase + 16 * ASTRIDE + ks * 32);
#pragma unroll
            for (int j = 0; j < 4; j++) {
                uint32_t b0 = b[j >> 1][(j & 1) ? 2 : 0];
                uint32_t b1 = b[j >> 1][(j & 1) ? 3 : 1];
                mma16816(acc[j], a, b0, b1);
            }
        }
    }

    int row0 = m0 + wm * 16 + (lane >> 2);
    int row1 = row0 + 8;
#pragma unroll
    for (int j = 0; j < 4; j++) {
        int col = n0 + wn * 32 + j * 8 + ((lane & 3) << 1);
        float v0 = acc[j][0], v1 = acc[j][1], v2 = acc[j][2], v3 = acc[j][3];
        if (bias) {
            float b0 = bias[col], b1 = bias[col + 1];
            v0 += b0; v1 += b1; v2 += b0; v3 += b1;
        }
        if (EPI == 3) {
            *(__half2*)(Ch + (size_t)row0 * N + col) =
                __halves2half2(__float2half_rn(v0), __float2half_rn(v1));
            *(__half2*)(Ch + (size_t)row1 * N + col) =
                __halves2half2(__float2half_rn(v2), __float2half_rn(v3));
        } else {
            if (EPI == 2) {
                float2 r0 = *(const float2*)(resid + (size_t)row0 * N + col);
                float2 r1 = *(const float2*)(resid + (size_t)row1 * N + col);
                v0 += r0.x; v1 += r0.y; v2 += r1.x; v3 += r1.y;
            }
            *(float2*)(Cf + (size_t)row0 * N + col) = make_float2(v0, v1);
            *(float2*)(Cf + (size_t)row1 * N + col) = make_float2(v2, v3);
        }
    }
}

// =================== host launch ===================
extern "C" void kernel_launch(void* const* d_in, const int* in_sizes, int n_in,
                              void* d_out, int out_size) {
    (void)in_sizes; (void)n_in; (void)out_size;
    const float* grd2sat = (const float*)d_in[0];
    const float* grd_x   = (const float*)d_in[1];
    const float* u       = (const float*)d_in[2];
    const float* ln_q_w  = (const float*)d_in[3];
    const float* ln_q_b  = (const float*)d_in[4];
    const float* ln_k_w  = (const float*)d_in[5];
    const float* ln_k_b  = (const float*)d_in[6];
    const float* ln_v_w  = (const float*)d_in[7];
    const float* ln_v_b  = (const float*)d_in[8];
    const float* Wq      = (const float*)d_in[9];
    const float* Wk      = (const float*)d_in[10];
    const float* Wv      = (const float*)d_in[11];
    const float* Wproj   = (const float*)d_in[12];
    const float* bproj   = (const float*)d_in[13];
    const float* ln_pre_w  = (const float*)d_in[14];
    const float* ln_pre_b  = (const float*)d_in[15];
    const float* Wm1     = (const float*)d_in[16];
    const float* bm1     = (const float*)d_in[17];
    const float* Wm2     = (const float*)d_in[18];
    const float* bm2     = (const float*)d_in[19];
    const float* ln_post_w = (const float*)d_in[20];
    const float* ln_post_b = (const float*)d_in[21];
    float* out = (float*)d_out;

    __half *Xn, *Wkv, *KVh, *t16, *q16, *a16, *z216, *h16, *Wq2, *Wp2, *Wm1c, *Wm2c;
    float *bcat, *x, *z1, *z2, *z3;
    cudaGetSymbolAddress((void**)&Xn, g_Xn);
    cudaGetSymbolAddress((void**)&Wkv, g_Wkv);
    cudaGetSymbolAddress((void**)&bcat, g_bcat);
    cudaGetSymbolAddress((void**)&KVh, g_KVh);
    cudaGetSymbolAddress((void**)&x, g_x);
    cudaGetSymbolAddress((void**)&t16, g_t16);
    cudaGetSymbolAddress((void**)&q16, g_q16);
    cudaGetSymbolAddress((void**)&a16, g_a16);
    cudaGetSymbolAddress((void**)&z1, g_z1);
    cudaGetSymbolAddress((void**)&z2, g_z2);
    cudaGetSymbolAddress((void**)&z216, g_z216);
    cudaGetSymbolAddress((void**)&h16, g_h16);
    cudaGetSymbolAddress((void**)&z3, g_z3);
    cudaGetSymbolAddress((void**)&Wq2, g_Wq2);
    cudaGetSymbolAddress((void**)&Wp2, g_Wp2);
    cudaGetSymbolAddress((void**)&Wm1c, g_Wm1c);
    cudaGetSymbolAddress((void**)&Wm2c, g_Wm2c);

    WtJobs jobs;
    for (int i = 0; i < 2; i++) {
        jobs.j[i * 4 + 0] = {Wq + i * 65536, Wq2 + i * 256 * 256, 256, 256, ATTN_SCALE};
        jobs.j[i * 4 + 1] = {Wproj + i * 65536, Wp2 + i * 256 * 256, 256, 256, 1.f};
        jobs.j[i * 4 + 2] = {Wm1 + i * 131072, Wm1c + i * 512 * 256, 256, 512, 1.f};
        jobs.j[i * 4 + 3] = {Wm2 + i * 131072, Wm2c + i * 256 * 512, 512, 256, 1.f};
    }

    // ---- prep (one fused kernel) ----
    prep_kernel<<<1280, 256>>>(grd_x, Wk, Wv, ln_k_w, ln_v_w, ln_k_b, ln_v_b,
                               Xn, Wkv, bcat, jobs);

    // KVh = f16(Xn @ Wkv + bcat) : (4096 x 1024)
    mma_gemm<3><<<dim3(16, 32), 256>>>(Xn, Wkv, bcat, nullptr, nullptr, KVh, 256, 1024);
    transpose_scale<<<dim3(128, 8), dim3(32, 8)>>>(grd2sat, x, 256, 4096);

    for (int i = 0; i < 2; i++) {
        if (i == 0)
            ln_kernel<<<512, 256>>>(x, ln_q_w, ln_q_b, nullptr, t16);
        mma_gemm64<3><<<dim3(4, 64), 256>>>(t16, Wq2 + i * 256 * 256, nullptr, nullptr,
                                            nullptr, q16, 256, 256);
        attn_kernel<<<4096, 256>>>(q16, KVh, u, i * 512, a16);
        mma_gemm64<0><<<dim3(4, 64), 256>>>(a16, Wp2 + i * 256 * 256, bproj + i * 256,
                                            nullptr, z1, nullptr, 256, 256);
        ln_kernel<<<512, 256>>>(z1, ln_pre_w + i * 256, ln_pre_b + i * 256, z2, z216);
        mma_gemm<1><<<dim3(8, 32), 256>>>(z216, Wm1c + i * 512 * 256, bm1 + i * 512,
                                          nullptr, nullptr, h16, 256, 512);
        mma_gemm64<2><<<dim3(4, 64), 256>>>(h16, Wm2c + i * 256 * 512, bm2 + i * 256, z2,
                                            z3, nullptr, 512, 256);
        if (i == 0)
            ln2_kernel<<<512, 256>>>(z3, ln_post_w, ln_post_b, ln_q_w + 256, ln_q_b + 256,
                                     t16);
    }

    final_kernel<<<128, 256>>>(z3, ln_post_w + 256, ln_post_b + 256, out);
}

// round 16
// speedup vs baseline: 1.2942x; 1.0272x over previous
#include <cuda_runtime.h>
#include <cuda_fp16.h>
#include <math.h>
#include <stdint.h>

#define ATTN_SCALE 0.17677669529663687f  // 32^-0.5

__device__ __forceinline__ uint32_t smem_u32(const void* p) {
    uint32_t a;
    asm("{ .reg .u64 t; cvta.to.shared.u64 t, %1; cvt.u32.u64 %0, t; }" : "=r"(a) : "l"(p));
    return a;
}
__device__ __forceinline__ void cp16(uint32_t s, const void* g) {
    asm volatile("cp.async.cg.shared.global [%0], [%1], 16;" :: "r"(s), "l"(g));
}
__device__ __forceinline__ void cp_commit() { asm volatile("cp.async.commit_group;"); }
__device__ __forceinline__ void cp_wait1() { asm volatile("cp.async.wait_group 1;"); }
__device__ __forceinline__ void ldsm4(uint32_t r[4], uint32_t addr) {
    asm volatile("ldmatrix.sync.aligned.m8n8.x4.shared.b16 {%0,%1,%2,%3}, [%4];"
                 : "=r"(r[0]), "=r"(r[1]), "=r"(r[2]), "=r"(r[3]) : "r"(addr));
}
__device__ __forceinline__ void mma16816(float c[4], const uint32_t a[4], uint32_t b0,
                                         uint32_t b1) {
    asm volatile(
        "mma.sync.aligned.m16n8k16.row.col.f32.f16.f16.f32 "
        "{%0,%1,%2,%3}, {%4,%5,%6,%7}, {%8,%9}, {%0,%1,%2,%3};"
        : "+f"(c[0]), "+f"(c[1]), "+f"(c[2]), "+f"(c[3])
        : "r"(a[0]), "r"(a[1]), "r"(a[2]), "r"(a[3]), "r"(b0), "r"(b1));
}

// =================== device scratch ===================
__device__ __half g_Xn[4096 * 256];
__device__ __half g_Wkv[1024 * 256];
__device__ float g_bcat[1024];
__device__ __half g_KVh[4096 * 1024];
__device__ float g_x[4096 * 256];
__device__ __half g_t16[4096 * 256];
__device__ __half g_q16[4096 * 256];
__device__ __half g_a16[4096 * 256];
__device__ float g_z1[4096 * 256];
__device__ float g_z2[4096 * 256];
__device__ __half g_z216[4096 * 256];
__device__ __half g_h16[4096 * 512];
__device__ float g_z3[4096 * 256];
__device__ __half g_Wq2[2 * 256 * 256];
__device__ __half g_Wp2[2 * 256 * 256];
__device__ __half g_Wm1c[2 * 512 * 256];
__device__ __half g_Wm2c[2 * 256 * 512];

// =================== fused prep kernel ===================
struct WtJob { const float* src; __half* dst; int K; int N; float scale; };
struct WtJobs { WtJob j[8]; };
__global__ __launch_bounds__(256) void prep_kernel(
    const float* __restrict__ grd_x,
    const float* __restrict__ Wk, const float* __restrict__ Wv,
    const float* __restrict__ lnkw, const float* __restrict__ lnvw,
    const float* __restrict__ lnkb, const float* __restrict__ lnvb,
    __half* __restrict__ Xn, __half* __restrict__ Wkv, float* __restrict__ bcat,
    WtJobs jobs) {
    __shared__ float tile[256][33];
    __shared__ float ps[8][32], pq[8][32];
    __shared__ float cmu[32], crs[32];
    int bid = blockIdx.x;
    int tid = threadIdx.x;
    int tx = tid & 31, ty = tid >> 5;

    if (bid < 128) {
        int j0 = bid * 32;
        float s = 0.f, q = 0.f;
#pragma unroll
        for (int t = 0; t < 32; t++) {
            int c = t * 8 + ty;
            float v = grd_x[(size_t)c * 4096 + j0 + tx];
            tile[c][tx] = v;
            s += v; q += v * v;
        }
        ps[ty][tx] = s; pq[ty][tx] = q;
        __syncthreads();
        if (ty == 0) {
            float ss = 0.f, qq = 0.f;
#pragma unroll
            for (int r = 0; r < 8; r++) { ss += ps[r][tx]; qq += pq[r][tx]; }
            float mu = ss * (1.f / 256.f);
            cmu[tx] = mu;
            crs[tx] = rsqrtf(qq * (1.f / 256.f) - mu * mu + 1e-5f);
        }
        __syncthreads();
#pragma unroll
        for (int r = 0; r < 4; r++) {
            int jj = ty * 4 + r;
            float mu = cmu[jj], rs = crs[jj];
            size_t rb = (size_t)(j0 + jj) * 256 + tx * 8;
            __half h[8];
#pragma unroll
            for (int e = 0; e < 8; e++)
                h[e] = __float2half_rn((tile[tx * 8 + e][jj] - mu) * rs);
            *(uint4*)(Xn + rb) = *(uint4*)h;
        }
    } else if (bid < 384) {
        int local = bid - 128;
        int ct = local & 7, ot = (local >> 3) & 7, seg = local >> 6;
        int i = seg >> 1, isv = seg & 1;
        const float* W = (isv ? Wv : Wk) + i * 65536;
        const float* lw = (isv ? lnvw : lnkw) + i * 256;
        int c0 = ct * 32, o0 = ot * 32;
        float (*t)[33] = (float (*)[33])tile;
#pragma unroll
        for (int s = 0; s < 4; s++) {
            int c = c0 + ty + s * 8;
            t[ty + s * 8][tx] = W[(size_t)c * 256 + o0 + tx] * lw[c];
        }
        __syncthreads();
#pragma unroll
        for (int s = 0; s < 4; s++) {
            int o = o0 + ty + s * 8;
            size_t rb = (size_t)(seg * 256 + o) * 256;
            Wkv[rb + c0 + tx] = __float2half_rn(t[tx][ty + s * 8]);
        }
    } else if (bid < 512) {
        int o = (bid - 384) * 8 + ty;
        int seg = o >> 8, oo = o & 255;
        int i = seg >> 1, isv = seg & 1;
        const float* W = (isv ? Wv : Wk) + i * 65536;
        const float* b = (isv ? lnvb : lnkb) + i * 256;
        float s = 0.f;
#pragma unroll
        for (int t = 0; t < 8; t++) {
            int c = tx + t * 32;
            s += b[c] * W[(size_t)c * 256 + oo];
        }
#pragma unroll
        for (int off = 16; off; off >>= 1) s += __shfl_xor_sync(0xffffffffu, s, off);
        if (tx == 0) bcat[o] = s;
    } else {
        int local = bid - 512;
        const int prefix[9] = {0, 64, 128, 256, 384, 448, 512, 640, 768};
        int jb = 0;
#pragma unroll
        for (int t = 1; t < 8; t++) if (local >= prefix[t]) jb = t;
        WtJob job = jobs.j[jb];
        int loc = local - prefix[jb];
        int ktiles = job.K >> 5;
        int kt = loc % ktiles, nt = loc / ktiles;
        int k0 = kt * 32, n0 = nt * 32;
        float (*t)[33] = (float (*)[33])tile;
#pragma unroll
        for (int s = 0; s < 4; s++) {
            int k = k0 + ty + s * 8;
            t[ty + s * 8][tx] = job.src[(size_t)k * job.N + n0 + tx] * job.scale;
        }
        __syncthreads();
#pragma unroll
        for (int s = 0; s < 4; s++) {
            int n = n0 + ty + s * 8;
            job.dst[(size_t)n * job.K + k0 + tx] = __float2half_rn(t[tx][ty + s * 8]);
        }
    }
}

// LayerNorm, warp per row; optional fp32 out and/or fp16 out
__global__ __launch_bounds__(256) void ln_kernel(const float* __restrict__ in,
                                                 const float* __restrict__ w,
                                                 const float* __restrict__ b,
                                                 float* __restrict__ outF,
                                                 __half* __restrict__ outH) {
    int wid = threadIdx.x >> 5, lane = threadIdx.x & 31;
    int m = blockIdx.x * 8 + wid;
    const float4* ip = (const float4*)(in + (size_t)m * 256 + lane * 8);
    float4 v0 = ip[0], v1 = ip[1];
    float s = v0.x + v0.y + v0.z + v0.w + v1.x + v1.y + v1.z + v1.w;
#pragma unroll
    for (int o = 16; o; o >>= 1) s += __shfl_xor_sync(0xffffffffu, s, o);
    float mean = s * (1.f / 256.f);
    float x[8] = {v0.x - mean, v0.y - mean, v0.z - mean, v0.w - mean,
                  v1.x - mean, v1.y - mean, v1.z - mean, v1.w - mean};
    float q = 0.f;
#pragma unroll
    for (int e = 0; e < 8; e++) q = fmaf(x[e], x[e], q);
#pragma unroll
    for (int o = 16; o; o >>= 1) q += __shfl_xor_sync(0xffffffffu, q, o);
    float rstd = rsqrtf(q * (1.f / 256.f) + 1e-5f);
    float4 w0 = *(const float4*)(w + lane * 8), w1 = *(const float4*)(w + lane * 8 + 4);
    float4 b0 = *(const float4*)(b + lane * 8), b1 = *(const float4*)(b + lane * 8 + 4);
    float y[8];
    y[0] = x[0] * rstd * w0.x + b0.x; y[1] = x[1] * rstd * w0.y + b0.y;
    y[2] = x[2] * rstd * w0.z + b0.z; y[3] = x[3] * rstd * w0.w + b0.w;
    y[4] = x[4] * rstd * w1.x + b1.x; y[5] = x[5] * rstd * w1.y + b1.y;
    y[6] = x[6] * rstd * w1.z + b1.z; y[7] = x[7] * rstd * w1.w + b1.w;
    if (outF) {
        float4* op = (float4*)(outF + (size_t)m * 256 + lane * 8);
        op[0] = make_float4(y[0], y[1], y[2], y[3]);
        op[1] = make_float4(y[4], y[5], y[6], y[7]);
    }
    if (outH) {
        __half h[8];
#pragma unroll
        for (int e = 0; e < 8; e++) h[e] = __float2half_rn(y[e]);
        *(uint4*)(outH + (size_t)m * 256 + lane * 8) = *(uint4*)h;
    }
}

// fused LN_post + LN_q at block boundary: z3 -> t16 (fp16)
__global__ __launch_bounds__(256) void ln2_kernel(const float* __restrict__ in,
                                                  const float* __restrict__ w1,
                                                  const float* __restrict__ b1,
                                                  const float* __restrict__ w2,
                                                  const float* __restrict__ b2,
                                                  __half* __restrict__ outH) {
    int wid = threadIdx.x >> 5, lane = threadIdx.x & 31;
    int m = blockIdx.x * 8 + wid;
    const float4* ip = (const float4*)(in + (size_t)m * 256 + lane * 8);
    float4 v0 = ip[0], v1 = ip[1];
    float x[8] = {v0.x, v0.y, v0.z, v0.w, v1.x, v1.y, v1.z, v1.w};
    float s = 0.f;
#pragma unroll
    for (int e = 0; e < 8; e++) s += x[e];
#pragma unroll
    for (int o = 16; o; o >>= 1) s += __shfl_xor_sync(0xffffffffu, s, o);
    float mean = s * (1.f / 256.f);
    float q = 0.f;
#pragma unroll
    for (int e = 0; e < 8; e++) { x[e] -= mean; q = fmaf(x[e], x[e], q); }
#pragma unroll
    for (int o = 16; o; o >>= 1) q += __shfl_xor_sync(0xffffffffu, q, o);
    float rstd = rsqrtf(q * (1.f / 256.f) + 1e-5f);
    float4 wA0 = *(const float4*)(w1 + lane * 8), wA1 = *(const float4*)(w1 + lane * 8 + 4);
    float4 bA0 = *(const float4*)(b1 + lane * 8), bA1 = *(const float4*)(b1 + lane * 8 + 4);
    float wa[8] = {wA0.x, wA0.y, wA0.z, wA0.w, wA1.x, wA1.y, wA1.z, wA1.w};
    float ba[8] = {bA0.x, bA0.y, bA0.z, bA0.w, bA1.x, bA1.y, bA1.z, bA1.w};
    float y[8];
#pragma unroll
    for (int e = 0; e < 8; e++) y[e] = x[e] * rstd * wa[e] + ba[e];
    float s2 = 0.f;
#pragma unroll
    for (int e = 0; e < 8; e++) s2 += y[e];
#pragma unroll
    for (int o = 16; o; o >>= 1) s2 += __shfl_xor_sync(0xffffffffu, s2, o);
    float mean2 = s2 * (1.f / 256.f);
    float q2 = 0.f;
#pragma unroll
    for (int e = 0; e < 8; e++) { y[e] -= mean2; q2 = fmaf(y[e], y[e], q2); }
#pragma unroll
    for (int o = 16; o; o >>= 1) q2 += __shfl_xor_sync(0xffffffffu, q2, o);
    float rstd2 = rsqrtf(q2 * (1.f / 256.f) + 1e-5f);
    float4 wB0 = *(const float4*)(w2 + lane * 8), wB1 = *(const float4*)(w2 + lane * 8 + 4);
    float4 bB0 = *(const float4*)(b2 + lane * 8), bB1 = *(const float4*)(b2 + lane * 8 + 4);
    float wb[8] = {wB0.x, wB0.y, wB0.z, wB0.w, wB1.x, wB1.y, wB1.z, wB1.w};
    float bb[8] = {bB0.x, bB0.y, bB0.z, bB0.w, bB1.x, bB1.y, bB1.z, bB1.w};
    __half h[8];
#pragma unroll
    for (int e = 0; e < 8; e++)
        h[e] = __float2half_rn(y[e] * rstd2 * wb[e] + bb[e]);
    *(uint4*)(outH + (size_t)m * 256 + lane * 8) = *(uint4*)h;
}

// fused final: z3 -> LN_post -> L2-normalize -> transposed out (256 x 4096)
__global__ __launch_bounds__(256) void final_kernel(const float* __restrict__ in,
                                                    const float* __restrict__ w,
                                                    const float* __restrict__ b,
                                                    float* __restrict__ out) {
    __shared__ float t[32][257];
    int tid = threadIdx.x;
    int wid = tid >> 5, lane = tid & 31;
    int m0 = blockIdx.x * 32;
#pragma unroll
    for (int r = 0; r < 4; r++) {
        int lr = wid * 4 + r;
        int m = m0 + lr;
        const float4* ip = (const float4*)(in + (size_t)m * 256 + lane * 8);
        float4 v0 = ip[0], v1 = ip[1];
        float x[8] = {v0.x, v0.y, v0.z, v0.w, v1.x, v1.y, v1.z, v1.w};
        float s = 0.f;
#pragma unroll
        for (int e = 0; e < 8; e++) s += x[e];
#pragma unroll
        for (int o = 16; o; o >>= 1) s += __shfl_xor_sync(0xffffffffu, s, o);
        float mean = s * (1.f / 256.f);
        float q = 0.f;
#pragma unroll
        for (int e = 0; e < 8; e++) { x[e] -= mean; q = fmaf(x[e], x[e], q); }
#pragma unroll
        for (int o = 16; o; o >>= 1) q += __shfl_xor_sync(0xffffffffu, q, o);
        float rstd = rsqrtf(q * (1.f / 256.f) + 1e-5f);
        float4 w0 = *(const float4*)(w + lane * 8), w1 = *(const float4*)(w + lane * 8 + 4);
        float4 b0 = *(const float4*)(b + lane * 8), b1 = *(const float4*)(b + lane * 8 + 4);
        float wa[8] = {w0.x, w0.y, w0.z, w0.w, w1.x, w1.y, w1.z, w1.w};
        float ba[8] = {b0.x, b0.y, b0.z, b0.w, b1.x, b1.y, b1.z, b1.w};
        float y[8];
        float q2 = 0.f;
#pragma unroll
        for (int e = 0; e < 8; e++) {
            y[e] = x[e] * rstd * wa[e] + ba[e];
            q2 = fmaf(y[e], y[e], q2);
        }
#pragma unroll
        for (int o = 16; o; o >>= 1) q2 += __shfl_xor_sync(0xffffffffu, q2, o);
        float inv = 1.f / fmaxf(sqrtf(q2), 1e-12f);
#pragma unroll
        for (int e = 0; e < 8; e++) t[lr][lane * 8 + e] = y[e] * inv;
    }
    __syncthreads();
    int tx = tid & 31, ty = tid >> 5;
#pragma unroll
    for (int c0 = 0; c0 < 256; c0 += 8) {
        int c = c0 + ty;
        out[(size_t)c * 4096 + m0 + tx] = t[tx][c];
    }
}

__global__ void transpose_scale(const float* __restrict__ in, float* __restrict__ out,
                                int R, int Cd) {
    __shared__ float t[32][33];
    int bx = blockIdx.x * 32, by = blockIdx.y * 32;
    int x = threadIdx.x, y0 = threadIdx.y;
    for (int yy = y0; yy < 32; yy += 8)
        t[yy][x] = in[(size_t)(by + yy) * Cd + bx + x];
    __syncthreads();
    for (int yy = y0; yy < 32; yy += 8)
        out[(size_t)(bx + yy) * R + by + x] = t[x][yy];
}

// =================== attention: 8 groups x 4 lanes, uint4 loads ====================
__global__ __launch_bounds__(256) void attn_kernel(const __half* __restrict__ q16,
                                                   const __half* __restrict__ KVh,
                                                   const float* __restrict__ u,
                                                   int kvOff,
                                                   __half* __restrict__ a16) {
    int m = blockIdx.x;
    int h = threadIdx.x >> 5;
    int lane = threadIdx.x & 31;
    int g = lane >> 2, e = lane & 3;   // 8 groups x 4 lanes; lane covers dims e*8..e*8+7
    float uf = floorf(u[m]);
    int jL = (int)fminf(fmaxf(uf, 0.f), 127.f);
    int jR = (int)fminf(fmaxf(uf + 1.f, 0.f), 127.f);
    int base = kvOff + h * 32 + e * 8;
    uint4 qraw = *(const uint4*)(q16 + (size_t)m * 256 + h * 32 + e * 8);
    float qv[8];
    {
        float2 f0 = __half22float2(*(const __half2*)&qraw.x);
        float2 f1 = __half22float2(*(const __half2*)&qraw.y);
        float2 f2 = __half22float2(*(const __half2*)&qraw.z);
        float2 f3 = __half22float2(*(const __half2*)&qraw.w);
        qv[0] = f0.x; qv[1] = f0.y; qv[2] = f1.x; qv[3] = f1.y;
        qv[4] = f2.x; qv[5] = f2.y; qv[6] = f3.x; qv[7] = f3.y;
    }

    float s[8];
#pragma unroll
    for (int t = 0; t < 8; t++) {
        int n = t * 8 + g;
        int j = ((n & 31) << 7) + ((n < 32) ? jL : jR);
        uint4 raw = *(const uint4*)(KVh + (size_t)j * 1024 + base);
        float2 f0 = __half22float2(*(const __half2*)&raw.x);
        float2 f1 = __half22float2(*(const __half2*)&raw.y);
        float2 f2 = __half22float2(*(const __half2*)&raw.z);
        float2 f3 = __half22float2(*(const __half2*)&raw.w);
        float p = qv[0] * f0.x + qv[1] * f0.y + qv[2] * f1.x + qv[3] * f1.y +
                  qv[4] * f2.x + qv[5] * f2.y + qv[6] * f3.x + qv[7] * f3.y;
        p += __shfl_xor_sync(0xffffffffu, p, 1);
        p += __shfl_xor_sync(0xffffffffu, p, 2);
        s[t] = p;
    }
    float mx = s[0];
#pragma unroll
    for (int t = 1; t < 8; t++) mx = fmaxf(mx, s[t]);
#pragma unroll
    for (int o = 16; o; o >>= 1) mx = fmaxf(mx, __shfl_xor_sync(0xffffffffu, mx, o));
    float sum = 0.f;
#pragma unroll
    for (int t = 0; t < 8; t++) { s[t] = expf(s[t] - mx); sum += s[t]; }
#pragma unroll
    for (int o = 16; o; o >>= 1) sum += __shfl_xor_sync(0xffffffffu, sum, o);
    float inv = 4.f / sum;   // each n replicated across the 4 lanes of its group

    float acc[8] = {0.f, 0.f, 0.f, 0.f, 0.f, 0.f, 0.f, 0.f};
#pragma unroll
    for (int t = 0; t < 8; t++) {
        int n = t * 8 + g;
        int j = ((n & 31) << 7) + ((n < 32) ? jL : jR);
        uint4 raw = *(const uint4*)(KVh + (size_t)j * 1024 + base + 256);
        float2 f0 = __half22float2(*(const __half2*)&raw.x);
        float2 f1 = __half22float2(*(const __half2*)&raw.y);
        float2 f2 = __half22float2(*(const __half2*)&raw.z);
        float2 f3 = __half22float2(*(const __half2*)&raw.w);
        float p = s[t] * inv;
        acc[0] = fmaf(p, f0.x, acc[0]); acc[1] = fmaf(p, f0.y, acc[1]);
        acc[2] = fmaf(p, f1.x, acc[2]); acc[3] = fmaf(p, f1.y, acc[3]);
        acc[4] = fmaf(p, f2.x, acc[4]); acc[5] = fmaf(p, f2.y, acc[5]);
        acc[6] = fmaf(p, f3.x, acc[6]); acc[7] = fmaf(p, f3.y, acc[7]);
    }
#pragma unroll
    for (int o = 4; o <= 16; o <<= 1) {
#pragma unroll
        for (int k = 0; k < 8; k++)
            acc[k] += __shfl_xor_sync(0xffffffffu, acc[k], o);
    }
    if (g == 0) {
        __half h8[8];
#pragma unroll
        for (int k = 0; k < 8; k++) h8[k] = __float2half_rn(acc[k]);
        *(uint4*)(a16 + (size_t)m * 256 + h * 32 + e * 8) = *(uint4*)h8;
    }
}

// =================== mma.sync fp16 GEMM: 128x64 tile, 3-stage =====================
// EPI 0: Cf = acc (+bias)  EPI 1: Ch = f16(gelu(acc+bias))  EPI 2: Cf = acc+bias+resid
// EPI 3: Ch = f16(acc+bias)
#define ASTRIDE 80
#define STAGE_BYTES 15360
#define NSTAGE 3
template <int EPI>
__global__ __launch_bounds__(256, 2) void mma_gemm(const __half* __restrict__ A,
                                                   const __half* __restrict__ B,
                                                   const float* __restrict__ bias,
                                                   const float* __restrict__ resid,
                                                   float* __restrict__ Cf,
                                                   __half* __restrict__ Ch,
                                                   int Krow, int N) {
    __shared__ __align__(16) char sm[NSTAGE * STAGE_BYTES];
    uint32_t smBase = smem_u32(sm);
    int tid = threadIdx.x;
    int wid = tid >> 5, lane = tid & 31;
    int wm = wid >> 1, wn = wid & 1;
    int m0 = blockIdx.y << 7, n0 = blockIdx.x << 6;
    int niter = Krow >> 5;

    float acc[2][4][4];
#pragma unroll
    for (int t = 0; t < 2; t++)
#pragma unroll
        for (int j = 0; j < 4; j++)
#pragma unroll
            for (int e = 0; e < 4; e++) acc[t][j][e] = 0.f;

    int arow = tid >> 2, ach = tid & 3;
    const __half* gA0 = A + (size_t)m0 * Krow;
    const __half* gB0 = B + (size_t)(n0 + arow) * Krow + (ach << 3);

    uint32_t aOff = (uint32_t)((wm * 32 + (lane & 15)) * ASTRIDE + ((lane >> 4) << 4));
    uint32_t bOff = (uint32_t)((wn * 32 + (lane & 7) + ((lane >> 4) << 3)) * ASTRIDE +
                               (((lane >> 3) & 1) << 4));

#pragma unroll
    for (int st = 0; st < NSTAGE - 1; st++) {
        uint32_t sA = smBase + st * STAGE_BYTES;
        int k0 = st << 5;
#pragma unroll
        for (int i = 0; i < 2; i++) {
            int u = tid + (i << 8);
            int row = u >> 2, ch = u & 3;
            cp16(sA + row * ASTRIDE + ch * 16, gA0 + (size_t)row * Krow + k0 + (ch << 3));
        }
        cp16(sA + 10240 + arow * ASTRIDE + ach * 16, gB0 + k0);
        cp_commit();
    }

    int stC = 0, stP = NSTAGE - 1;
    for (int it = 0; it < niter; ++it) {
        cp_wait1();
        __syncthreads();
        if (it + NSTAGE - 1 < niter) {
            int k0 = (it + NSTAGE - 1) << 5;
            uint32_t sA = smBase + stP * STAGE_BYTES;
#pragma unroll
            for (int i = 0; i < 2; i++) {
                int u = tid + (i << 8);
                int row = u >> 2, ch = u & 3;
                cp16(sA + row * ASTRIDE + ch * 16, gA0 + (size_t)row * Krow + k0 + (ch << 3));
            }
            cp16(sA + 10240 + arow * ASTRIDE + ach * 16, gB0 + k0);
        }
        cp_commit();
        if (++stP == NSTAGE) stP = 0;

        uint32_t aBase = smBase + stC * STAGE_BYTES + aOff;
        uint32_t bBase = smBase + stC * STAGE_BYTES + 10240 + bOff;
        if (++stC == NSTAGE) stC = 0;
#pragma unroll
        for (int ks = 0; ks < 2; ks++) {
            uint32_t a[2][4], b[2][4];
            ldsm4(a[0], aBase + ks * 32);
            ldsm4(a[1], aBase + 16 * ASTRIDE + ks * 32);
            ldsm4(b[0], bBase + ks * 32);
            ldsm4(b[1], bBase + 16 * ASTRIDE + ks * 32);
#pragma unroll
            for (int t = 0; t < 2; t++) {
#pragma unroll
                for (int j = 0; j < 4; j++) {
                    uint32_t b0 = b[j >> 1][(j & 1) ? 2 : 0];
                    uint32_t b1 = b[j >> 1][(j & 1) ? 3 : 1];
                    mma16816(acc[t][j], a[t], b0, b1);
                }
            }
        }
    }

#pragma unroll
    for (int t = 0; t < 2; t++) {
        int row0 = m0 + wm * 32 + t * 16 + (lane >> 2);
        int row1 = row0 + 8;
#pragma unroll
        for (int j = 0; j < 4; j++) {
            int col = n0 + wn * 32 + j * 8 + ((lane & 3) << 1);
            float v0 = acc[t][j][0], v1 = acc[t][j][1];
            float v2 = acc[t][j][2], v3 = acc[t][j][3];
            if (EPI != 0 || bias) {
                float b0 = bias[col], b1 = bias[col + 1];
                v0 += b0; v1 += b1; v2 += b0; v3 += b1;
            }
            if (EPI == 1 || EPI == 3) {
                if (EPI == 1) {
                    v0 = 0.5f * v0 * (1.f + erff(v0 * 0.70710678118654752f));
                    v1 = 0.5f * v1 * (1.f + erff(v1 * 0.70710678118654752f));
                    v2 = 0.5f * v2 * (1.f + erff(v2 * 0.70710678118654752f));
                    v3 = 0.5f * v3 * (1.f + erff(v3 * 0.70710678118654752f));
                }
                *(__half2*)(Ch + (size_t)row0 * N + col) =
                    __halves2half2(__float2half_rn(v0), __float2half_rn(v1));
                *(__half2*)(Ch + (size_t)row1 * N + col) =
                    __halves2half2(__float2half_rn(v2), __float2half_rn(v3));
            } else {
                if (EPI == 2) {
                    float2 r0 = *(const float2*)(resid + (size_t)row0 * N + col);
                    float2 r1 = *(const float2*)(resid + (size_t)row1 * N + col);
                    v0 += r0.x; v1 += r0.y; v2 += r1.x; v3 += r1.y;
                }
                *(float2*)(Cf + (size_t)row0 * N + col) = make_float2(v0, v1);
                *(float2*)(Cf + (size_t)row1 * N + col) = make_float2(v2, v3);
            }
        }
    }
}

// =================== 64x64-tile variant (for N=256 GEMMs) ==========================
// EPI 0: Cf = acc (+bias)   EPI 2: Cf = acc+bias+resid   EPI 3: Ch = f16(acc (+bias))
#define STAGE64 10240
template <int EPI>
__global__ __launch_bounds__(256, 3) void mma_gemm64(const __half* __restrict__ A,
                                                     const __half* __restrict__ B,
                                                     const float* __restrict__ bias,
                                                     const float* __restrict__ resid,
                                                     float* __restrict__ Cf,
                                                     __half* __restrict__ Ch,
                                                     int Krow, int N) {
    __shared__ __align__(16) char sm[NSTAGE * STAGE64];
    uint32_t smBase = smem_u32(sm);
    int tid = threadIdx.x;
    int wid = tid >> 5, lane = tid & 31;
    int wm = wid >> 1, wn = wid & 1;
    int m0 = blockIdx.y << 6, n0 = blockIdx.x << 6;
    int niter = Krow >> 5;

    float acc[4][4];
#pragma unroll
    for (int j = 0; j < 4; j++)
#pragma unroll
        for (int e = 0; e < 4; e++) acc[j][e] = 0.f;

    int arow = tid >> 2, ach = tid & 3;
    const __half* gA0 = A + (size_t)(m0 + arow) * Krow + (ach << 3);
    const __half* gB0 = B + (size_t)(n0 + arow) * Krow + (ach << 3);
    uint32_t sOff = arow * ASTRIDE + (ach << 4);

    uint32_t aOff = (uint32_t)((wm * 16 + (lane & 15)) * ASTRIDE + ((lane >> 4) << 4));
    uint32_t bOff = (uint32_t)(5120 + (wn * 32 + (lane & 7) + ((lane >> 4) << 3)) * ASTRIDE +
                               (((lane >> 3) & 1) << 4));

#pragma unroll
    for (int st = 0; st < NSTAGE - 1; st++) {
        uint32_t sA = smBase + st * STAGE64;
        int k0 = st << 5;
        cp16(sA + sOff, gA0 + k0);
        cp16(sA + 5120 + sOff, gB0 + k0);
        cp_commit();
    }

    int stC = 0, stP = NSTAGE - 1;
    for (int it = 0; it < niter; ++it) {
        cp_wait1();
        __syncthreads();
        if (it + NSTAGE - 1 < niter) {
            int k0 = (it + NSTAGE - 1) << 5;
            uint32_t sA = smBase + stP * STAGE64;
            cp16(sA + sOff, gA0 + k0);
            cp16(sA + 5120 + sOff, gB0 + k0);
        }
        cp_commit();
        if (++stP == NSTAGE) stP = 0;

        uint32_t aBase = smBase + stC * STAGE64 + aOff;
        uint32_t bBase = smBase + stC * STAGE64 + bOff;
        if (++stC == NSTAGE) stC = 0;
#pragma unroll
        for (int ks = 0; ks < 2; ks++) {
            uint32_t a[4], b[2][4];
            ldsm4(a, aBase + ks * 32);
            ldsm4(b[0], bBase + ks * 32);
            ldsm4(b[1], bBase + 16 * ASTRIDE + ks * 32);
#pragma unroll
            for (int j = 0; j < 4; j++) {
                uint32_t b0 = b[j >> 1][(j & 1) ? 2 : 0];
                uint32_t b1 = b[j >> 1][(j & 1) ? 3 : 1];
                mma16816(acc[j], a, b0, b1);
            }
        }
    }

    int row0 = m0 + wm * 16 + (lane >> 2);
    int row1 = row0 + 8;
#pragma unroll
    for (int j = 0; j < 4; j++) {
        int col = n0 + wn * 32 + j * 8 + ((lane & 3) << 1);
        float v0 = acc[j][0], v1 = acc[j][1], v2 = acc[j][2], v3 = acc[j][3];
        if (bias) {
            float b0 = bias[col], b1 = bias[col + 1];
            v0 += b0; v1 += b1; v2 += b0; v3 += b1;
        }
        if (EPI == 3) {
            *(__half2*)(Ch + (size_t)row0 * N + col) =
                __halves2half2(__float2half_rn(v0), __float2half_rn(v1));
            *(__half2*)(Ch + (size_t)row1 * N + col) =
                __halves2half2(__float2half_rn(v2), __float2half_rn(v3));
        } else {
            if (EPI == 2) {
                float2 r0 = *(const float2*)(resid + (size_t)row0 * N + col);
                float2 r1 = *(const float2*)(resid + (size_t)row1 * N + col);
                v0 += r0.x; v1 += r0.y; v2 += r1.x; v3 += r1.y;
            }
            *(float2*)(Cf + (size_t)row0 * N + col) = make_float2(v0, v1);
            *(float2*)(Cf + (size_t)row1 * N + col) = make_float2(v2, v3);
        }
    }
}

// =================== host launch ===================
extern "C" void kernel_launch(void* const* d_in, const int* in_sizes, int n_in,
                              void* d_out, int out_size) {
    (void)in_sizes; (void)n_in; (void)out_size;
    const float* grd2sat = (const float*)d_in[0];
    const float* grd_x   = (const float*)d_in[1];
    const float* u       = (const float*)d_in[2];
    const float* ln_q_w  = (const float*)d_in[3];
    const float* ln_q_b  = (const float*)d_in[4];
    const float* ln_k_w  = (const float*)d_in[5];
    const float* ln_k_b  = (const float*)d_in[6];
    const float* ln_v_w  = (const float*)d_in[7];
    const float* ln_v_b  = (const float*)d_in[8];
    const float* Wq      = (const float*)d_in[9];
    const float* Wk      = (const float*)d_in[10];
    const float* Wv      = (const float*)d_in[11];
    const float* Wproj   = (const float*)d_in[12];
    const float* bproj   = (const float*)d_in[13];
    const float* ln_pre_w  = (const float*)d_in[14];
    const float* ln_pre_b  = (const float*)d_in[15];
    const float* Wm1     = (const float*)d_in[16];
    const float* bm1     = (const float*)d_in[17];
    const float* Wm2     = (const float*)d_in[18];
    const float* bm2     = (const float*)d_in[19];
    const float* ln_post_w = (const float*)d_in[20];
    const float* ln_post_b = (const float*)d_in[21];
    float* out = (float*)d_out;

    __half *Xn, *Wkv, *KVh, *t16, *q16, *a16, *z216, *h16, *Wq2, *Wp2, *Wm1c, *Wm2c;
    float *bcat, *x, *z1, *z2, *z3;
    cudaGetSymbolAddress((void**)&Xn, g_Xn);
    cudaGetSymbolAddress((void**)&Wkv, g_Wkv);
    cudaGetSymbolAddress((void**)&bcat, g_bcat);
    cudaGetSymbolAddress((void**)&KVh, g_KVh);
    cudaGetSymbolAddress((void**)&x, g_x);
    cudaGetSymbolAddress((void**)&t16, g_t16);
    cudaGetSymbolAddress((void**)&q16, g_q16);
    cudaGetSymbolAddress((void**)&a16, g_a16);
    cudaGetSymbolAddress((void**)&z1, g_z1);
    cudaGetSymbolAddress((void**)&z2, g_z2);
    cudaGetSymbolAddress((void**)&z216, g_z216);
    cudaGetSymbolAddress((void**)&h16, g_h16);
    cudaGetSymbolAddress((void**)&z3, g_z3);
    cudaGetSymbolAddress((void**)&Wq2, g_Wq2);
    cudaGetSymbolAddress((void**)&Wp2, g_Wp2);
    cudaGetSymbolAddress((void**)&Wm1c, g_Wm1c);
    cudaGetSymbolAddress((void**)&Wm2c, g_Wm2c);

    WtJobs jobs;
    for (int i = 0; i < 2; i++) {
        jobs.j[i * 4 + 0] = {Wq + i * 65536, Wq2 + i * 256 * 256, 256, 256, ATTN_SCALE};
        jobs.j[i * 4 + 1] = {Wproj + i * 65536, Wp2 + i * 256 * 256, 256, 256, 1.f};
        jobs.j[i * 4 + 2] = {Wm1 + i * 131072, Wm1c + i * 512 * 256, 256, 512, 1.f};
        jobs.j[i * 4 + 3] = {Wm2 + i * 131072, Wm2c + i * 256 * 512, 512, 256, 1.f};
    }

    // ---- prep (one fused kernel) ----
    prep_kernel<<<1280, 256>>>(grd_x, Wk, Wv, ln_k_w, ln_v_w, ln_k_b, ln_v_b,
                               Xn, Wkv, bcat, jobs);

    // KVh = f16(Xn @ Wkv + bcat) : (4096 x 1024)
    mma_gemm<3><<<dim3(16, 32), 256>>>(Xn, Wkv, bcat, nullptr, nullptr, KVh, 256, 1024);
    transpose_scale<<<dim3(128, 8), dim3(32, 8)>>>(grd2sat, x, 256, 4096);

    for (int i = 0; i < 2; i++) {
        if (i == 0)
            ln_kernel<<<512, 256>>>(x, ln_q_w, ln_q_b, nullptr, t16);
        mma_gemm64<3><<<dim3(4, 64), 256>>>(t16, Wq2 + i * 256 * 256, nullptr, nullptr,
                                            nullptr, q16, 256, 256);
        attn_kernel<<<4096, 256>>>(q16, KVh, u, i * 512, a16);
        mma_gemm64<0><<<dim3(4, 64), 256>>>(a16, Wp2 + i * 256 * 256, bproj + i * 256,
                                            nullptr, z1, nullptr, 256, 256);
        ln_kernel<<<512, 256>>>(z1, ln_pre_w + i * 256, ln_pre_b + i * 256, z2, z216);
        mma_gemm<1><<<dim3(8, 32), 256>>>(z216, Wm1c + i * 512 * 256, bm1 + i * 512,
                                          nullptr, nullptr, h16, 256, 512);
        mma_gemm64<2><<<dim3(4, 64), 256>>>(h16, Wm2c + i * 256 * 512, bm2 + i * 256, z2,
                                            z3, nullptr, 512, 256);
        if (i == 0)
            ln2_kernel<<<512, 256>>>(z3, ln_post_w, ln_post_b, ln_q_w + 256, ln_q_b + 256,
                                     t16);
    }

    final_kernel<<<128, 256>>>(z3, ln_post_w + 256, ln_post_b + 256, out);
}

// round 17
// speedup vs baseline: 1.3266x; 1.0250x over previous
#include <cuda_runtime.h>
#include <cuda_fp16.h>
#include <math.h>
#include <stdint.h>

#define ATTN_SCALE 0.17677669529663687f  // 32^-0.5

__device__ __forceinline__ uint32_t smem_u32(const void* p) {
    uint32_t a;
    asm("{ .reg .u64 t; cvta.to.shared.u64 t, %1; cvt.u32.u64 %0, t; }" : "=r"(a) : "l"(p));
    return a;
}
__device__ __forceinline__ void cp16(uint32_t s, const void* g) {
    asm volatile("cp.async.cg.shared.global [%0], [%1], 16;" :: "r"(s), "l"(g));
}
__device__ __forceinline__ void cp_commit() { asm volatile("cp.async.commit_group;"); }
__device__ __forceinline__ void cp_wait1() { asm volatile("cp.async.wait_group 1;"); }
__device__ __forceinline__ void ldsm4(uint32_t r[4], uint32_t addr) {
    asm volatile("ldmatrix.sync.aligned.m8n8.x4.shared.b16 {%0,%1,%2,%3}, [%4];"
                 : "=r"(r[0]), "=r"(r[1]), "=r"(r[2]), "=r"(r[3]) : "r"(addr));
}
__device__ __forceinline__ void mma16816(float c[4], const uint32_t a[4], uint32_t b0,
                                         uint32_t b1) {
    asm volatile(
        "mma.sync.aligned.m16n8k16.row.col.f32.f16.f16.f32 "
        "{%0,%1,%2,%3}, {%4,%5,%6,%7}, {%8,%9}, {%0,%1,%2,%3};"
        : "+f"(c[0]), "+f"(c[1]), "+f"(c[2]), "+f"(c[3])
        : "r"(a[0]), "r"(a[1]), "r"(a[2]), "r"(a[3]), "r"(b0), "r"(b1));
}

// =================== device scratch ===================
__device__ __half g_Xn[4096 * 256];
__device__ __half g_Wkv[1024 * 256];
__device__ float g_bcat[1024];
__device__ __half g_KVh[4096 * 1024];
__device__ float g_x[4096 * 256];
__device__ __half g_t16[4096 * 256];
__device__ __half g_q16[4096 * 256];
__device__ __half g_a16[4096 * 256];
__device__ float g_z1[4096 * 256];
__device__ __half g_z216[4096 * 256];
__device__ __half g_h16[4096 * 512];
__device__ float g_z3[4096 * 256];
__device__ __half g_Wq2[2 * 256 * 256];
__device__ __half g_Wp2[2 * 256 * 256];
__device__ __half g_Wm1c[2 * 512 * 256];
__device__ __half g_Wm2c[2 * 256 * 512];

// =================== fused prep kernel ===================
struct WtJob { const float* src; __half* dst; int K; int N; float scale; };
struct WtJobs { WtJob j[8]; };
__global__ __launch_bounds__(256) void prep_kernel(
    const float* __restrict__ grd_x,
    const float* __restrict__ Wk, const float* __restrict__ Wv,
    const float* __restrict__ lnkw, const float* __restrict__ lnvw,
    const float* __restrict__ lnkb, const float* __restrict__ lnvb,
    __half* __restrict__ Xn, __half* __restrict__ Wkv, float* __restrict__ bcat,
    WtJobs jobs) {
    __shared__ float tile[256][33];
    __shared__ float ps[8][32], pq[8][32];
    __shared__ float cmu[32], crs[32];
    int bid = blockIdx.x;
    int tid = threadIdx.x;
    int tx = tid & 31, ty = tid >> 5;

    if (bid < 128) {
        int j0 = bid * 32;
        float s = 0.f, q = 0.f;
#pragma unroll
        for (int t = 0; t < 32; t++) {
            int c = t * 8 + ty;
            float v = grd_x[(size_t)c * 4096 + j0 + tx];
            tile[c][tx] = v;
            s += v; q += v * v;
        }
        ps[ty][tx] = s; pq[ty][tx] = q;
        __syncthreads();
        if (ty == 0) {
            float ss = 0.f, qq = 0.f;
#pragma unroll
            for (int r = 0; r < 8; r++) { ss += ps[r][tx]; qq += pq[r][tx]; }
            float mu = ss * (1.f / 256.f);
            cmu[tx] = mu;
            crs[tx] = rsqrtf(qq * (1.f / 256.f) - mu * mu + 1e-5f);
        }
        __syncthreads();
#pragma unroll
        for (int r = 0; r < 4; r++) {
            int jj = ty * 4 + r;
            float mu = cmu[jj], rs = crs[jj];
            size_t rb = (size_t)(j0 + jj) * 256 + tx * 8;
            __half h[8];
#pragma unroll
            for (int e = 0; e < 8; e++)
                h[e] = __float2half_rn((tile[tx * 8 + e][jj] - mu) * rs);
            *(uint4*)(Xn + rb) = *(uint4*)h;
        }
    } else if (bid < 384) {
        int local = bid - 128;
        int ct = local & 7, ot = (local >> 3) & 7, seg = local >> 6;
        int i = seg >> 1, isv = seg & 1;
        const float* W = (isv ? Wv : Wk) + i * 65536;
        const float* lw = (isv ? lnvw : lnkw) + i * 256;
        int c0 = ct * 32, o0 = ot * 32;
        float (*t)[33] = (float (*)[33])tile;
#pragma unroll
        for (int s = 0; s < 4; s++) {
            int c = c0 + ty + s * 8;
            t[ty + s * 8][tx] = W[(size_t)c * 256 + o0 + tx] * lw[c];
        }
        __syncthreads();
#pragma unroll
        for (int s = 0; s < 4; s++) {
            int o = o0 + ty + s * 8;
            size_t rb = (size_t)(seg * 256 + o) * 256;
            Wkv[rb + c0 + tx] = __float2half_rn(t[tx][ty + s * 8]);
        }
    } else if (bid < 512) {
        int o = (bid - 384) * 8 + ty;
        int seg = o >> 8, oo = o & 255;
        int i = seg >> 1, isv = seg & 1;
        const float* W = (isv ? Wv : Wk) + i * 65536;
        const float* b = (isv ? lnvb : lnkb) + i * 256;
        float s = 0.f;
#pragma unroll
        for (int t = 0; t < 8; t++) {
            int c = tx + t * 32;
            s += b[c] * W[(size_t)c * 256 + oo];
        }
#pragma unroll
        for (int off = 16; off; off >>= 1) s += __shfl_xor_sync(0xffffffffu, s, off);
        if (tx == 0) bcat[o] = s;
    } else {
        int local = bid - 512;
        const int prefix[9] = {0, 64, 128, 256, 384, 448, 512, 640, 768};
        int jb = 0;
#pragma unroll
        for (int t = 1; t < 8; t++) if (local >= prefix[t]) jb = t;
        WtJob job = jobs.j[jb];
        int loc = local - prefix[jb];
        int ktiles = job.K >> 5;
        int kt = loc % ktiles, nt = loc / ktiles;
        int k0 = kt * 32, n0 = nt * 32;
        float (*t)[33] = (float (*)[33])tile;
#pragma unroll
        for (int s = 0; s < 4; s++) {
            int k = k0 + ty + s * 8;
            t[ty + s * 8][tx] = job.src[(size_t)k * job.N + n0 + tx] * job.scale;
        }
        __syncthreads();
#pragma unroll
        for (int s = 0; s < 4; s++) {
            int n = n0 + ty + s * 8;
            job.dst[(size_t)n * job.K + k0 + tx] = __float2half_rn(t[tx][ty + s * 8]);
        }
    }
}

// LayerNorm, warp per row; optional fp32 out and/or fp16 out
__global__ __launch_bounds__(256) void ln_kernel(const float* __restrict__ in,
                                                 const float* __restrict__ w,
                                                 const float* __restrict__ b,
                                                 float* __restrict__ outF,
                                                 __half* __restrict__ outH) {
    int wid = threadIdx.x >> 5, lane = threadIdx.x & 31;
    int m = blockIdx.x * 8 + wid;
    const float4* ip = (const float4*)(in + (size_t)m * 256 + lane * 8);
    float4 v0 = ip[0], v1 = ip[1];
    float s = v0.x + v0.y + v0.z + v0.w + v1.x + v1.y + v1.z + v1.w;
#pragma unroll
    for (int o = 16; o; o >>= 1) s += __shfl_xor_sync(0xffffffffu, s, o);
    float mean = s * (1.f / 256.f);
    float x[8] = {v0.x - mean, v0.y - mean, v0.z - mean, v0.w - mean,
                  v1.x - mean, v1.y - mean, v1.z - mean, v1.w - mean};
    float q = 0.f;
#pragma unroll
    for (int e = 0; e < 8; e++) q = fmaf(x[e], x[e], q);
#pragma unroll
    for (int o = 16; o; o >>= 1) q += __shfl_xor_sync(0xffffffffu, q, o);
    float rstd = rsqrtf(q * (1.f / 256.f) + 1e-5f);
    float4 w0 = *(const float4*)(w + lane * 8), w1 = *(const float4*)(w + lane * 8 + 4);
    float4 b0 = *(const float4*)(b + lane * 8), b1 = *(const float4*)(b + lane * 8 + 4);
    float y[8];
    y[0] = x[0] * rstd * w0.x + b0.x; y[1] = x[1] * rstd * w0.y + b0.y;
    y[2] = x[2] * rstd * w0.z + b0.z; y[3] = x[3] * rstd * w0.w + b0.w;
    y[4] = x[4] * rstd * w1.x + b1.x; y[5] = x[5] * rstd * w1.y + b1.y;
    y[6] = x[6] * rstd * w1.z + b1.z; y[7] = x[7] * rstd * w1.w + b1.w;
    if (outF) {
        float4* op = (float4*)(outF + (size_t)m * 256 + lane * 8);
        op[0] = make_float4(y[0], y[1], y[2], y[3]);
        op[1] = make_float4(y[4], y[5], y[6], y[7]);
    }
    if (outH) {
        __half h[8];
#pragma unroll
        for (int e = 0; e < 8; e++) h[e] = __float2half_rn(y[e]);
        *(uint4*)(outH + (size_t)m * 256 + lane * 8) = *(uint4*)h;
    }
}

// fused LN_post + LN_q at block boundary: z3 -> t16 (fp16)
__global__ __launch_bounds__(256) void ln2_kernel(const float* __restrict__ in,
                                                  const float* __restrict__ w1,
                                                  const float* __restrict__ b1,
                                                  const float* __restrict__ w2,
                                                  const float* __restrict__ b2,
                                                  __half* __restrict__ outH) {
    int wid = threadIdx.x >> 5, lane = threadIdx.x & 31;
    int m = blockIdx.x * 8 + wid;
    const float4* ip = (const float4*)(in + (size_t)m * 256 + lane * 8);
    float4 v0 = ip[0], v1 = ip[1];
    float x[8] = {v0.x, v0.y, v0.z, v0.w, v1.x, v1.y, v1.z, v1.w};
    float s = 0.f;
#pragma unroll
    for (int e = 0; e < 8; e++) s += x[e];
#pragma unroll
    for (int o = 16; o; o >>= 1) s += __shfl_xor_sync(0xffffffffu, s, o);
    float mean = s * (1.f / 256.f);
    float q = 0.f;
#pragma unroll
    for (int e = 0; e < 8; e++) { x[e] -= mean; q = fmaf(x[e], x[e], q); }
#pragma unroll
    for (int o = 16; o; o >>= 1) q += __shfl_xor_sync(0xffffffffu, q, o);
    float rstd = rsqrtf(q * (1.f / 256.f) + 1e-5f);
    float4 wA0 = *(const float4*)(w1 + lane * 8), wA1 = *(const float4*)(w1 + lane * 8 + 4);
    float4 bA0 = *(const float4*)(b1 + lane * 8), bA1 = *(const float4*)(b1 + lane * 8 + 4);
    float wa[8] = {wA0.x, wA0.y, wA0.z, wA0.w, wA1.x, wA1.y, wA1.z, wA1.w};
    float ba[8] = {bA0.x, bA0.y, bA0.z, bA0.w, bA1.x, bA1.y, bA1.z, bA1.w};
    float y[8];
#pragma unroll
    for (int e = 0; e < 8; e++) y[e] = x[e] * rstd * wa[e] + ba[e];
    float s2 = 0.f;
#pragma unroll
    for (int e = 0; e < 8; e++) s2 += y[e];
#pragma unroll
    for (int o = 16; o; o >>= 1) s2 += __shfl_xor_sync(0xffffffffu, s2, o);
    float mean2 = s2 * (1.f / 256.f);
    float q2 = 0.f;
#pragma unroll
    for (int e = 0; e < 8; e++) { y[e] -= mean2; q2 = fmaf(y[e], y[e], q2); }
#pragma unroll
    for (int o = 16; o; o >>= 1) q2 += __shfl_xor_sync(0xffffffffu, q2, o);
    float rstd2 = rsqrtf(q2 * (1.f / 256.f) + 1e-5f);
    float4 wB0 = *(const float4*)(w2 + lane * 8), wB1 = *(const float4*)(w2 + lane * 8 + 4);
    float4 bB0 = *(const float4*)(b2 + lane * 8), bB1 = *(const float4*)(b2 + lane * 8 + 4);
    float wb[8] = {wB0.x, wB0.y, wB0.z, wB0.w, wB1.x, wB1.y, wB1.z, wB1.w};
    float bb[8] = {bB0.x, bB0.y, bB0.z, bB0.w, bB1.x, bB1.y, bB1.z, bB1.w};
    __half h[8];
#pragma unroll
    for (int e = 0; e < 8; e++)
        h[e] = __float2half_rn(y[e] * rstd2 * wb[e] + bb[e]);
    *(uint4*)(outH + (size_t)m * 256 + lane * 8) = *(uint4*)h;
}

// fused final: z3 -> LN_post -> L2-normalize -> transposed out (256 x 4096)
__global__ __launch_bounds__(256) void final_kernel(const float* __restrict__ in,
                                                    const float* __restrict__ w,
                                                    const float* __restrict__ b,
                                                    float* __restrict__ out) {
    __shared__ float t[32][257];
    int tid = threadIdx.x;
    int wid = tid >> 5, lane = tid & 31;
    int m0 = blockIdx.x * 32;
#pragma unroll
    for (int r = 0; r < 4; r++) {
        int lr = wid * 4 + r;
        int m = m0 + lr;
        const float4* ip = (const float4*)(in + (size_t)m * 256 + lane * 8);
        float4 v0 = ip[0], v1 = ip[1];
        float x[8] = {v0.x, v0.y, v0.z, v0.w, v1.x, v1.y, v1.z, v1.w};
        float s = 0.f;
#pragma unroll
        for (int e = 0; e < 8; e++) s += x[e];
#pragma unroll
        for (int o = 16; o; o >>= 1) s += __shfl_xor_sync(0xffffffffu, s, o);
        float mean = s * (1.f / 256.f);
        float q = 0.f;
#pragma unroll
        for (int e = 0; e < 8; e++) { x[e] -= mean; q = fmaf(x[e], x[e], q); }
#pragma unroll
        for (int o = 16; o; o >>= 1) q += __shfl_xor_sync(0xffffffffu, q, o);
        float rstd = rsqrtf(q * (1.f / 256.f) + 1e-5f);
        float4 w0 = *(const float4*)(w + lane * 8), w1 = *(const float4*)(w + lane * 8 + 4);
        float4 b0 = *(const float4*)(b + lane * 8), b1 = *(const float4*)(b + lane * 8 + 4);
        float wa[8] = {w0.x, w0.y, w0.z, w0.w, w1.x, w1.y, w1.z, w1.w};
        float ba[8] = {b0.x, b0.y, b0.z, b0.w, b1.x, b1.y, b1.z, b1.w};
        float y[8];
        float q2 = 0.f;
#pragma unroll
        for (int e = 0; e < 8; e++) {
            y[e] = x[e] * rstd * wa[e] + ba[e];
            q2 = fmaf(y[e], y[e], q2);
        }
#pragma unroll
        for (int o = 16; o; o >>= 1) q2 += __shfl_xor_sync(0xffffffffu, q2, o);
        float inv = 1.f / fmaxf(sqrtf(q2), 1e-12f);
#pragma unroll
        for (int e = 0; e < 8; e++) t[lr][lane * 8 + e] = y[e] * inv;
    }
    __syncthreads();
    int tx = tid & 31, ty = tid >> 5;
#pragma unroll
    for (int c0 = 0; c0 < 256; c0 += 8) {
        int c = c0 + ty;
        out[(size_t)c * 4096 + m0 + tx] = t[tx][c];
    }
}

__global__ void transpose_scale(const float* __restrict__ in, float* __restrict__ out,
                                int R, int Cd) {
    __shared__ float t[32][33];
    int bx = blockIdx.x * 32, by = blockIdx.y * 32;
    int x = threadIdx.x, y0 = threadIdx.y;
    for (int yy = y0; yy < 32; yy += 8)
        t[yy][x] = in[(size_t)(by + yy) * Cd + bx + x];
    __syncthreads();
    for (int yy = y0; yy < 32; yy += 8)
        out[(size_t)(bx + yy) * R + by + x] = t[x][yy];
}

// =================== attention: 8 groups x 4 lanes, uint4 loads ====================
__global__ __launch_bounds__(256) void attn_kernel(const __half* __restrict__ q16,
                                                   const __half* __restrict__ KVh,
                                                   const float* __restrict__ u,
                                                   int kvOff,
                                                   __half* __restrict__ a16) {
    int m = blockIdx.x;
    int h = threadIdx.x >> 5;
    int lane = threadIdx.x & 31;
    int g = lane >> 2, e = lane & 3;   // 8 groups x 4 lanes; lane covers dims e*8..e*8+7
    float uf = floorf(u[m]);
    int jL = (int)fminf(fmaxf(uf, 0.f), 127.f);
    int jR = (int)fminf(fmaxf(uf + 1.f, 0.f), 127.f);
    int base = kvOff + h * 32 + e * 8;
    uint4 qraw = *(const uint4*)(q16 + (size_t)m * 256 + h * 32 + e * 8);
    float qv[8];
    {
        float2 f0 = __half22float2(*(const __half2*)&qraw.x);
        float2 f1 = __half22float2(*(const __half2*)&qraw.y);
        float2 f2 = __half22float2(*(const __half2*)&qraw.z);
        float2 f3 = __half22float2(*(const __half2*)&qraw.w);
        qv[0] = f0.x; qv[1] = f0.y; qv[2] = f1.x; qv[3] = f1.y;
        qv[4] = f2.x; qv[5] = f2.y; qv[6] = f3.x; qv[7] = f3.y;
    }

    float s[8];
#pragma unroll
    for (int t = 0; t < 8; t++) {
        int n = t * 8 + g;
        int j = ((n & 31) << 7) + ((n < 32) ? jL : jR);
        uint4 raw = *(const uint4*)(KVh + (size_t)j * 1024 + base);
        float2 f0 = __half22float2(*(const __half2*)&raw.x);
        float2 f1 = __half22float2(*(const __half2*)&raw.y);
        float2 f2 = __half22float2(*(const __half2*)&raw.z);
        float2 f3 = __half22float2(*(const __half2*)&raw.w);
        float p = qv[0] * f0.x + qv[1] * f0.y + qv[2] * f1.x + qv[3] * f1.y +
                  qv[4] * f2.x + qv[5] * f2.y + qv[6] * f3.x + qv[7] * f3.y;
        p += __shfl_xor_sync(0xffffffffu, p, 1);
        p += __shfl_xor_sync(0xffffffffu, p, 2);
        s[t] = p;
    }
    float mx = s[0];
#pragma unroll
    for (int t = 1; t < 8; t++) mx = fmaxf(mx, s[t]);
#pragma unroll
    for (int o = 16; o; o >>= 1) mx = fmaxf(mx, __shfl_xor_sync(0xffffffffu, mx, o));
    float sum = 0.f;
#pragma unroll
    for (int t = 0; t < 8; t++) { s[t] = expf(s[t] - mx); sum += s[t]; }
#pragma unroll
    for (int o = 16; o; o >>= 1) sum += __shfl_xor_sync(0xffffffffu, sum, o);
    float inv = 4.f / sum;   // each n replicated across the 4 lanes of its group

    float acc[8] = {0.f, 0.f, 0.f, 0.f, 0.f, 0.f, 0.f, 0.f};
#pragma unroll
    for (int t = 0; t < 8; t++) {
        int n = t * 8 + g;
        int j = ((n & 31) << 7) + ((n < 32) ? jL : jR);
        uint4 raw = *(const uint4*)(KVh + (size_t)j * 1024 + base + 256);
        float2 f0 = __half22float2(*(const __half2*)&raw.x);
        float2 f1 = __half22float2(*(const __half2*)&raw.y);
        float2 f2 = __half22float2(*(const __half2*)&raw.z);
        float2 f3 = __half22float2(*(const __half2*)&raw.w);
        float p = s[t] * inv;
        acc[0] = fmaf(p, f0.x, acc[0]); acc[1] = fmaf(p, f0.y, acc[1]);
        acc[2] = fmaf(p, f1.x, acc[2]); acc[3] = fmaf(p, f1.y, acc[3]);
        acc[4] = fmaf(p, f2.x, acc[4]); acc[5] = fmaf(p, f2.y, acc[5]);
        acc[6] = fmaf(p, f3.x, acc[6]); acc[7] = fmaf(p, f3.y, acc[7]);
    }
#pragma unroll
    for (int o = 4; o <= 16; o <<= 1) {
#pragma unroll
        for (int k = 0; k < 8; k++)
            acc[k] += __shfl_xor_sync(0xffffffffu, acc[k], o);
    }
    if (g == 0) {
        __half h8[8];
#pragma unroll
        for (int k = 0; k < 8; k++) h8[k] = __float2half_rn(acc[k]);
        *(uint4*)(a16 + (size_t)m * 256 + h * 32 + e * 8) = *(uint4*)h8;
    }
}

// =================== mma.sync fp16 GEMM: 128x64 tile, 3-stage =====================
// EPI 0: Cf = acc (+bias)  EPI 1: Ch = f16(gelu(acc+bias))  EPI 3: Ch = f16(acc+bias)
#define ASTRIDE 80
#define STAGE_BYTES 15360
#define NSTAGE 3
template <int EPI>
__global__ __launch_bounds__(256, 2) void mma_gemm(const __half* __restrict__ A,
                                                   const __half* __restrict__ B,
                                                   const float* __restrict__ bias,
                                                   float* __restrict__ Cf,
                                                   __half* __restrict__ Ch,
                                                   int Krow, int N) {
    __shared__ __align__(16) char sm[NSTAGE * STAGE_BYTES];
    uint32_t smBase = smem_u32(sm);
    int tid = threadIdx.x;
    int wid = tid >> 5, lane = tid & 31;
    int wm = wid >> 1, wn = wid & 1;
    int m0 = blockIdx.y << 7, n0 = blockIdx.x << 6;
    int niter = Krow >> 5;

    float acc[2][4][4];
#pragma unroll
    for (int t = 0; t < 2; t++)
#pragma unroll
        for (int j = 0; j < 4; j++)
#pragma unroll
            for (int e = 0; e < 4; e++) acc[t][j][e] = 0.f;

    int arow = tid >> 2, ach = tid & 3;
    const __half* gA0 = A + (size_t)m0 * Krow;
    const __half* gB0 = B + (size_t)(n0 + arow) * Krow + (ach << 3);

    uint32_t aOff = (uint32_t)((wm * 32 + (lane & 15)) * ASTRIDE + ((lane >> 4) << 4));
    uint32_t bOff = (uint32_t)((wn * 32 + (lane & 7) + ((lane >> 4) << 3)) * ASTRIDE +
                               (((lane >> 3) & 1) << 4));

#pragma unroll
    for (int st = 0; st < NSTAGE - 1; st++) {
        uint32_t sA = smBase + st * STAGE_BYTES;
        int k0 = st << 5;
#pragma unroll
        for (int i = 0; i < 2; i++) {
            int u = tid + (i << 8);
            int row = u >> 2, ch = u & 3;
            cp16(sA + row * ASTRIDE + ch * 16, gA0 + (size_t)row * Krow + k0 + (ch << 3));
        }
        cp16(sA + 10240 + arow * ASTRIDE + ach * 16, gB0 + k0);
        cp_commit();
    }

    int stC = 0, stP = NSTAGE - 1;
    for (int it = 0; it < niter; ++it) {
        cp_wait1();
        __syncthreads();
        if (it + NSTAGE - 1 < niter) {
            int k0 = (it + NSTAGE - 1) << 5;
            uint32_t sA = smBase + stP * STAGE_BYTES;
#pragma unroll
            for (int i = 0; i < 2; i++) {
                int u = tid + (i << 8);
                int row = u >> 2, ch = u & 3;
                cp16(sA + row * ASTRIDE + ch * 16, gA0 + (size_t)row * Krow + k0 + (ch << 3));
            }
            cp16(sA + 10240 + arow * ASTRIDE + ach * 16, gB0 + k0);
        }
        cp_commit();
        if (++stP == NSTAGE) stP = 0;

        uint32_t aBase = smBase + stC * STAGE_BYTES + aOff;
        uint32_t bBase = smBase + stC * STAGE_BYTES + 10240 + bOff;
        if (++stC == NSTAGE) stC = 0;
#pragma unroll
        for (int ks = 0; ks < 2; ks++) {
            uint32_t a[2][4], b[2][4];
            ldsm4(a[0], aBase + ks * 32);
            ldsm4(a[1], aBase + 16 * ASTRIDE + ks * 32);
            ldsm4(b[0], bBase + ks * 32);
            ldsm4(b[1], bBase + 16 * ASTRIDE + ks * 32);
#pragma unroll
            for (int t = 0; t < 2; t++) {
#pragma unroll
                for (int j = 0; j < 4; j++) {
                    uint32_t b0 = b[j >> 1][(j & 1) ? 2 : 0];
                    uint32_t b1 = b[j >> 1][(j & 1) ? 3 : 1];
                    mma16816(acc[t][j], a[t], b0, b1);
                }
            }
        }
    }

#pragma unroll
    for (int t = 0; t < 2; t++) {
        int row0 = m0 + wm * 32 + t * 16 + (lane >> 2);
        int row1 = row0 + 8;
#pragma unroll
        for (int j = 0; j < 4; j++) {
            int col = n0 + wn * 32 + j * 8 + ((lane & 3) << 1);
            float v0 = acc[t][j][0], v1 = acc[t][j][1];
            float v2 = acc[t][j][2], v3 = acc[t][j][3];
            if (EPI != 0 || bias) {
                float b0 = bias[col], b1 = bias[col + 1];
                v0 += b0; v1 += b1; v2 += b0; v3 += b1;
            }
            if (EPI == 1 || EPI == 3) {
                if (EPI == 1) {
                    v0 = 0.5f * v0 * (1.f + erff(v0 * 0.70710678118654752f));
                    v1 = 0.5f * v1 * (1.f + erff(v1 * 0.70710678118654752f));
                    v2 = 0.5f * v2 * (1.f + erff(v2 * 0.70710678118654752f));
                    v3 = 0.5f * v3 * (1.f + erff(v3 * 0.70710678118654752f));
                }
                *(__half2*)(Ch + (size_t)row0 * N + col) =
                    __halves2half2(__float2half_rn(v0), __float2half_rn(v1));
                *(__half2*)(Ch + (size_t)row1 * N + col) =
                    __halves2half2(__float2half_rn(v2), __float2half_rn(v3));
            } else {
                *(float2*)(Cf + (size_t)row0 * N + col) = make_float2(v0, v1);
                *(float2*)(Cf + (size_t)row1 * N + col) = make_float2(v2, v3);
            }
        }
    }
}

// =================== 64x64-tile variant (for N=256 GEMMs) ==========================
// EPI 0: Cf = acc (+bias)   EPI 2: Cf = acc+bias+f32(residH)   EPI 3: Ch = f16(acc+bias)
#define STAGE64 10240
template <int EPI>
__global__ __launch_bounds__(256, 3) void mma_gemm64(const __half* __restrict__ A,
                                                     const __half* __restrict__ B,
                                                     const float* __restrict__ bias,
                                                     const __half* __restrict__ residH,
                                                     float* __restrict__ Cf,
                                                     __half* __restrict__ Ch,
                                                     int Krow, int N) {
    __shared__ __align__(16) char sm[NSTAGE * STAGE64];
    uint32_t smBase = smem_u32(sm);
    int tid = threadIdx.x;
    int wid = tid >> 5, lane = tid & 31;
    int wm = wid >> 1, wn = wid & 1;
    int m0 = blockIdx.y << 6, n0 = blockIdx.x << 6;
    int niter = Krow >> 5;

    float acc[4][4];
#pragma unroll
    for (int j = 0; j < 4; j++)
#pragma unroll
        for (int e = 0; e < 4; e++) acc[j][e] = 0.f;

    int arow = tid >> 2, ach = tid & 3;
    const __half* gA0 = A + (size_t)(m0 + arow) * Krow + (ach << 3);
    const __half* gB0 = B + (size_t)(n0 + arow) * Krow + (ach << 3);
    uint32_t sOff = arow * ASTRIDE + (ach << 4);

    uint32_t aOff = (uint32_t)((wm * 16 + (lane & 15)) * ASTRIDE + ((lane >> 4) << 4));
    uint32_t bOff = (uint32_t)(5120 + (wn * 32 + (lane & 7) + ((lane >> 4) << 3)) * ASTRIDE +
                               (((lane >> 3) & 1) << 4));

#pragma unroll
    for (int st = 0; st < NSTAGE - 1; st++) {
        uint32_t sA = smBase + st * STAGE64;
        int k0 = st << 5;
        cp16(sA + sOff, gA0 + k0);
        cp16(sA + 5120 + sOff, gB0 + k0);
        cp_commit();
    }

    int stC = 0, stP = NSTAGE - 1;
    for (int it = 0; it < niter; ++it) {
        cp_wait1();
        __syncthreads();
        if (it + NSTAGE - 1 < niter) {
            int k0 = (it + NSTAGE - 1) << 5;
            uint32_t sA = smBase + stP * STAGE64;
            cp16(sA + sOff, gA0 + k0);
            cp16(sA + 5120 + sOff, gB0 + k0);
        }
        cp_commit();
        if (++stP == NSTAGE) stP = 0;

        uint32_t aBase = smBase + stC * STAGE64 + aOff;
        uint32_t bBase = smBase + stC * STAGE64 + bOff;
        if (++stC == NSTAGE) stC = 0;
#pragma unroll
        for (int ks = 0; ks < 2; ks++) {
            uint32_t a[4], b[2][4];
            ldsm4(a, aBase + ks * 32);
            ldsm4(b[0], bBase + ks * 32);
            ldsm4(b[1], bBase + 16 * ASTRIDE + ks * 32);
#pragma unroll
            for (int j = 0; j < 4; j++) {
                uint32_t b0 = b[j >> 1][(j & 1) ? 2 : 0];
                uint32_t b1 = b[j >> 1][(j & 1) ? 3 : 1];
                mma16816(acc[j], a, b0, b1);
            }
        }
    }

    int row0 = m0 + wm * 16 + (lane >> 2);
    int row1 = row0 + 8;
#pragma unroll
    for (int j = 0; j < 4; j++) {
        int col = n0 + wn * 32 + j * 8 + ((lane & 3) << 1);
        float v0 = acc[j][0], v1 = acc[j][1], v2 = acc[j][2], v3 = acc[j][3];
        if (bias) {
            float b0 = bias[col], b1 = bias[col + 1];
            v0 += b0; v1 += b1; v2 += b0; v3 += b1;
        }
        if (EPI == 3) {
            *(__half2*)(Ch + (size_t)row0 * N + col) =
                __halves2half2(__float2half_rn(v0), __float2half_rn(v1));
            *(__half2*)(Ch + (size_t)row1 * N + col) =
                __halves2half2(__float2half_rn(v2), __float2half_rn(v3));
        } else {
            if (EPI == 2) {
                float2 r0 = __half22float2(*(const __half2*)(residH + (size_t)row0 * N + col));
                float2 r1 = __half22float2(*(const __half2*)(residH + (size_t)row1 * N + col));
                v0 += r0.x; v1 += r0.y; v2 += r1.x; v3 += r1.y;
            }
            *(float2*)(Cf + (size_t)row0 * N + col) = make_float2(v0, v1);
            *(float2*)(Cf + (size_t)row1 * N + col) = make_float2(v2, v3);
        }
    }
}

// =================== host launch ===================
extern "C" void kernel_launch(void* const* d_in, const int* in_sizes, int n_in,
                              void* d_out, int out_size) {
    (void)in_sizes; (void)n_in; (void)out_size;
    const float* grd2sat = (const float*)d_in[0];
    const float* grd_x   = (const float*)d_in[1];
    const float* u       = (const float*)d_in[2];
    const float* ln_q_w  = (const float*)d_in[3];
    const float* ln_q_b  = (const float*)d_in[4];
    const float* ln_k_w  = (const float*)d_in[5];
    const float* ln_k_b  = (const float*)d_in[6];
    const float* ln_v_w  = (const float*)d_in[7];
    const float* ln_v_b  = (const float*)d_in[8];
    const float* Wq      = (const float*)d_in[9];
    const float* Wk      = (const float*)d_in[10];
    const float* Wv      = (const float*)d_in[11];
    const float* Wproj   = (const float*)d_in[12];
    const float* bproj   = (const float*)d_in[13];
    const float* ln_pre_w  = (const float*)d_in[14];
    const float* ln_pre_b  = (const float*)d_in[15];
    const float* Wm1     = (const float*)d_in[16];
    const float* bm1     = (const float*)d_in[17];
    const float* Wm2     = (const float*)d_in[18];
    const float* bm2     = (const float*)d_in[19];
    const float* ln_post_w = (const float*)d_in[20];
    const float* ln_post_b = (const float*)d_in[21];
    float* out = (float*)d_out;

    __half *Xn, *Wkv, *KVh, *t16, *q16, *a16, *z216, *h16, *Wq2, *Wp2, *Wm1c, *Wm2c;
    float *bcat, *x, *z1, *z3;
    cudaGetSymbolAddress((void**)&Xn, g_Xn);
    cudaGetSymbolAddress((void**)&Wkv, g_Wkv);
    cudaGetSymbolAddress((void**)&bcat, g_bcat);
    cudaGetSymbolAddress((void**)&KVh, g_KVh);
    cudaGetSymbolAddress((void**)&x, g_x);
    cudaGetSymbolAddress((void**)&t16, g_t16);
    cudaGetSymbolAddress((void**)&q16, g_q16);
    cudaGetSymbolAddress((void**)&a16, g_a16);
    cudaGetSymbolAddress((void**)&z1, g_z1);
    cudaGetSymbolAddress((void**)&z216, g_z216);
    cudaGetSymbolAddress((void**)&h16, g_h16);
    cudaGetSymbolAddress((void**)&z3, g_z3);
    cudaGetSymbolAddress((void**)&Wq2, g_Wq2);
    cudaGetSymbolAddress((void**)&Wp2, g_Wp2);
    cudaGetSymbolAddress((void**)&Wm1c, g_Wm1c);
    cudaGetSymbolAddress((void**)&Wm2c, g_Wm2c);

    WtJobs jobs;
    for (int i = 0; i < 2; i++) {
        jobs.j[i * 4 + 0] = {Wq + i * 65536, Wq2 + i * 256 * 256, 256, 256, ATTN_SCALE};
        jobs.j[i * 4 + 1] = {Wproj + i * 65536, Wp2 + i * 256 * 256, 256, 256, 1.f};
        jobs.j[i * 4 + 2] = {Wm1 + i * 131072, Wm1c + i * 512 * 256, 256, 512, 1.f};
        jobs.j[i * 4 + 3] = {Wm2 + i * 131072, Wm2c + i * 256 * 512, 512, 256, 1.f};
    }

    // ---- prep (one fused kernel) ----
    prep_kernel<<<1280, 256>>>(grd_x, Wk, Wv, ln_k_w, ln_v_w, ln_k_b, ln_v_b,
                               Xn, Wkv, bcat, jobs);

    // KVh = f16(Xn @ Wkv + bcat) : (4096 x 1024)
    mma_gemm<3><<<dim3(16, 32), 256>>>(Xn, Wkv, bcat, nullptr, KVh, 256, 1024);
    transpose_scale<<<dim3(128, 8), dim3(32, 8)>>>(grd2sat, x, 256, 4096);

    for (int i = 0; i < 2; i++) {
        if (i == 0)
            ln_kernel<<<512, 256>>>(x, ln_q_w, ln_q_b, nullptr, t16);
        mma_gemm64<3><<<dim3(4, 64), 256>>>(t16, Wq2 + i * 256 * 256, nullptr, nullptr,
                                            nullptr, q16, 256, 256);
        attn_kernel<<<4096, 256>>>(q16, KVh, u, i * 512, a16);
        mma_gemm64<0><<<dim3(4, 64), 256>>>(a16, Wp2 + i * 256 * 256, bproj + i * 256,
                                            nullptr, z1, nullptr, 256, 256);
        ln_kernel<<<512, 256>>>(z1, ln_pre_w + i * 256, ln_pre_b + i * 256, nullptr, z216);
        mma_gemm<1><<<dim3(8, 32), 256>>>(z216, Wm1c + i * 512 * 256, bm1 + i * 512,
                                          nullptr, h16, 256, 512);
        mma_gemm64<2><<<dim3(4, 64), 256>>>(h16, Wm2c + i * 256 * 512, bm2 + i * 256,
                                            z216, z3, nullptr, 512, 256);
        if (i == 0)
            ln2_kernel<<<512, 256>>>(z3, ln_post_w, ln_post_b, ln_q_w + 256, ln_q_b + 256,
                                     t16);
    }

    final_kernel<<<128, 256>>>(z3, ln_post_w + 256, ln_post_b + 256, out);
}